// round 14
// baseline (speedup 1.0000x reference)
#include <cuda_runtime.h>
#include <cuda_bf16.h>
#include <cuda_fp16.h>
#include <math.h>
#include <cstdint>

// Problem shape constants
constexpr int SEQ  = 2048;
constexpr int DIM  = 4096;
constexpr int NH   = 32;
constexpr int NKV  = 8;
constexpr int HDIM = 128;

// Scratch (device globals: allocation-free rule)
__device__ float g_Q[SEQ * NH * HDIM];     // fp32 QKV-GEMM outputs
__device__ float g_K[SEQ * NKV * HDIM];
__device__ float g_V[SEQ * NKV * HDIM];

// Split-bf16 operands (16B-aligned for cp.async)
__device__ __align__(256) __nv_bfloat16 g_Xhi[SEQ * DIM];
__device__ __align__(256) __nv_bfloat16 g_Xlo[SEQ * DIM];
__device__ __align__(256) __nv_bfloat16 g_Wqkvt_hi[6144 * DIM];
__device__ __align__(256) __nv_bfloat16 g_Wqkvt_lo[6144 * DIM];
// fp16 operands for the 1-term output projection
__device__ __align__(256) __half g_Wot_h[DIM * DIM];   // [N=4096][K=4096] = Wo^T, fp16
__device__ __align__(256) __half g_Ch_hi[SEQ * DIM];   // attention out, fp16
// Split bf16 Q/K/V for HMMA attention (RoPE + scale folded into Q)
__device__ __align__(256) __nv_bfloat16 g_Qhi[SEQ * NH * HDIM];
__device__ __align__(256) __nv_bfloat16 g_Qlo[SEQ * NH * HDIM];
__device__ __align__(256) __nv_bfloat16 g_Khi[SEQ * NKV * HDIM];
__device__ __align__(256) __nv_bfloat16 g_Klo[SEQ * NKV * HDIM];
__device__ __align__(256) __nv_bfloat16 g_Vhi[SEQ * NKV * HDIM];
__device__ __align__(256) __nv_bfloat16 g_Vlo[SEQ * NKV * HDIM];

// ===========================================================================
// PTX helpers
// ===========================================================================
__device__ __forceinline__ uint32_t smem_to_u32(const void* smem_ptr) {
    uint32_t addr;
    asm("{ .reg .u64 tmp; cvta.to.shared.u64 tmp, %1; cvt.u32.u64 %0, tmp; }"
        : "=r"(addr) : "l"(smem_ptr));
    return addr;
}
__device__ __forceinline__ void cp16(uint32_t dst, const void* src) {
    asm volatile("cp.async.cg.shared.global [%0], [%1], 16;\n" :: "r"(dst), "l"(src));
}
#define CP_COMMIT() asm volatile("cp.async.commit_group;\n" ::: "memory")
#define CP_WAIT(n)  asm volatile("cp.async.wait_group %0;\n" :: "n"(n) : "memory")

#define LDSM_OP(r0, r1, r2, r3, addr) \
    asm volatile("ldmatrix.sync.aligned.m8n8.x4.shared.b16 {%0,%1,%2,%3}, [%4];" \
        : "=r"(r0), "=r"(r1), "=r"(r2), "=r"(r3) : "r"(addr))
#define LDSM2_OP(r0, r1, addr) \
    asm volatile("ldmatrix.sync.aligned.m8n8.x2.shared.b16 {%0,%1}, [%2];" \
        : "=r"(r0), "=r"(r1) : "r"(addr))
#define LDSMT_OP(r0, r1, r2, r3, addr) \
    asm volatile("ldmatrix.sync.aligned.m8n8.x4.trans.shared.b16 {%0,%1,%2,%3}, [%4];" \
        : "=r"(r0), "=r"(r1), "=r"(r2), "=r"(r3) : "r"(addr))

#define MMA_OP(d0, d1, d2, d3, A0, A1, A2, A3, B0, B1) \
    asm volatile("mma.sync.aligned.m16n8k16.row.col.f32.bf16.bf16.f32 " \
        "{%0,%1,%2,%3}, {%4,%5,%6,%7}, {%8,%9}, {%0,%1,%2,%3};" \
        : "+f"(d0), "+f"(d1), "+f"(d2), "+f"(d3) \
        : "r"(A0), "r"(A1), "r"(A2), "r"(A3), "r"(B0), "r"(B1))

#define MMAH_OP(d0, d1, d2, d3, A0, A1, A2, A3, B0, B1) \
    asm volatile("mma.sync.aligned.m16n8k16.row.col.f32.f16.f16.f32 " \
        "{%0,%1,%2,%3}, {%4,%5,%6,%7}, {%8,%9}, {%0,%1,%2,%3};" \
        : "+f"(d0), "+f"(d1), "+f"(d2), "+f"(d3) \
        : "r"(A0), "r"(A1), "r"(A2), "r"(A3), "r"(B0), "r"(B1))

// ===========================================================================
// Split conversions
// ===========================================================================
__device__ __forceinline__ void split1(float x, __nv_bfloat16& h, __nv_bfloat16& l) {
    h = __float2bfloat16(x);
    l = __float2bfloat16(x - __bfloat162float(h));
}
__device__ __forceinline__ void packsplit(float x, float y, uint32_t& hi, uint32_t& lo) {
    uint32_t hx = (uint32_t)__bfloat16_as_ushort(__float2bfloat16(x));
    uint32_t hy = (uint32_t)__bfloat16_as_ushort(__float2bfloat16(y));
    float rx = x - __uint_as_float(hx << 16);
    float ry = y - __uint_as_float(hy << 16);
    uint32_t lx = (uint32_t)__bfloat16_as_ushort(__float2bfloat16(rx));
    uint32_t ly = (uint32_t)__bfloat16_as_ushort(__float2bfloat16(ry));
    hi = (hy << 16) | hx;
    lo = (ly << 16) | lx;
}

__global__ void xsplit_kernel(const float* __restrict__ X, int total4) {
    int idx = blockIdx.x * blockDim.x + threadIdx.x;
    if (idx >= total4) return;
    float4 v = ((const float4*)X)[idx];
    __nv_bfloat16 h0, h1, h2, h3, l0, l1, l2, l3;
    split1(v.x, h0, l0); split1(v.y, h1, l1);
    split1(v.z, h2, l2); split1(v.w, h3, l3);
    __nv_bfloat162* H2 = (__nv_bfloat162*)(g_Xhi + (size_t)idx * 4);
    __nv_bfloat162* L2 = (__nv_bfloat162*)(g_Xlo + (size_t)idx * 4);
    H2[0] = __nv_bfloat162(h0, h1); H2[1] = __nv_bfloat162(h2, h3);
    L2[0] = __nv_bfloat162(l0, l1); L2[1] = __nv_bfloat162(l2, l3);
}

// QKV weights: transpose + bf16 hi/lo split
__global__ void wsplit_t_kernel(const float* __restrict__ W, int N, int dst_row_off) {
    __shared__ float s[32][33];
    int n0 = blockIdx.x * 32, k0 = blockIdx.y * 32;
    int lx = threadIdx.x & 31, ly = threadIdx.x >> 5;
#pragma unroll
    for (int r = 0; r < 4; r++) {
        int row = ly + r * 8;
        s[row][lx] = W[(size_t)(k0 + row) * N + n0 + lx];
    }
    __syncthreads();
#pragma unroll
    for (int r = 0; r < 4; r++) {
        int nrow = ly + r * 8;
        float x = s[lx][nrow];
        __nv_bfloat16 h, l; split1(x, h, l);
        size_t o = (size_t)(dst_row_off + n0 + nrow) * DIM + k0 + lx;
        g_Wqkvt_hi[o] = h; g_Wqkvt_lo[o] = l;
    }
}

// Wo: transpose + fp16 (1-term out-projection)
__global__ void wsplit_wo_kernel(const float* __restrict__ W) {
    __shared__ float s[32][33];
    int n0 = blockIdx.x * 32, k0 = blockIdx.y * 32;
    int lx = threadIdx.x & 31, ly = threadIdx.x >> 5;
#pragma unroll
    for (int r = 0; r < 4; r++) {
        int row = ly + r * 8;
        s[row][lx] = W[(size_t)(k0 + row) * DIM + n0 + lx];
    }
    __syncthreads();
#pragma unroll
    for (int r = 0; r < 4; r++) {
        int nrow = ly + r * 8;
        g_Wot_h[(size_t)(n0 + nrow) * DIM + k0 + lx] = __float2half_rn(s[lx][nrow]);
    }
}

// ===========================================================================
// QKV GEMM: CTA 128x256, BK=32, 512 threads / 16 warps (4m x 4n), warp tile
// 32x64. 3-term split-bf16. A frags (x4) reused across 8 n-frags; B loaded
// as x2 (halved register residency). smem row = 32 bf16 = 4 x 16B chunks,
// swizzle ch ^= (row>>1)&3. Flipping k16 flips exactly offset bit 5 (^32).
// 3 stages x 48KB = 144KB, single barrier per iteration.
// ===========================================================================
constexpr int QBUF_A   = 8192;                 // 128 rows x 64B
constexpr int QBUF_B   = 16384;                // 256 rows x 64B
constexpr int QSTG     = 2 * QBUF_A + 2 * QBUF_B;  // 48KB
constexpr int QKV_SMEM = 3 * QSTG;                 // 144KB

__device__ __forceinline__ uint32_t qsw(int row, int ch) {
    return (uint32_t)(row * 64 + ((ch ^ ((row >> 1) & 3)) << 4));
}
__device__ __forceinline__ void q_load_a(uint32_t dbase, const __nv_bfloat16* g,
                                         int k0, int tid) {
    int row = tid >> 2, ch = tid & 3;
    cp16(dbase + qsw(row, ch), g + (size_t)row * DIM + k0 + ch * 8);
}
__device__ __forceinline__ void q_load_b(uint32_t dbase, const __nv_bfloat16* g,
                                         int k0, int tid) {
#pragma unroll
    for (int j = 0; j < 2; j++) {
        int c = tid * 2 + j;            // 0..1023
        int row = c >> 2, ch = c & 3;
        cp16(dbase + qsw(row, ch), g + (size_t)row * DIM + k0 + ch * 8);
    }
}
__device__ __forceinline__ void q_load_stage(
    uint32_t sbase, int s, int k0,
    const __nv_bfloat16* Ahi, const __nv_bfloat16* Alo,
    const __nv_bfloat16* Bhi, const __nv_bfloat16* Blo, int tid)
{
    uint32_t st = sbase + (uint32_t)s * QSTG;
    q_load_a(st,                     Ahi, k0, tid);
    q_load_a(st + QBUF_A,            Alo, k0, tid);
    q_load_b(st + 2 * QBUF_A,        Bhi, k0, tid);
    q_load_b(st + 2 * QBUF_A + QBUF_B, Blo, k0, tid);
}

#define DECL_ACC(m, n) \
    float c##m##n##_0 = 0.f, c##m##n##_1 = 0.f, c##m##n##_2 = 0.f, c##m##n##_3 = 0.f
#define DECL_F(p, n) uint32_t p##n##_0, p##n##_1, p##n##_2, p##n##_3

// One nf-pair at one k16: 4 x2 B loads + 12 term-grouped MMAs (dep gap 3)
#define Q_NFP(na, nb, KX) do { \
    uint32_t bA0, bA1, bB0, bB1, lA0, lA1, lB0, lB1; \
    LDSM2_OP(bA0, bA1, Bh + (bo##na ^ (KX))); \
    LDSM2_OP(bB0, bB1, Bh + (bo##nb ^ (KX))); \
    LDSM2_OP(lA0, lA1, Bl + (bo##na ^ (KX))); \
    LDSM2_OP(lB0, lB1, Bl + (bo##nb ^ (KX))); \
    MMA_OP(c0##na##_0, c0##na##_1, c0##na##_2, c0##na##_3, \
           ah0_0, ah0_1, ah0_2, ah0_3, bA0, bA1); \
    MMA_OP(c0##nb##_0, c0##nb##_1, c0##nb##_2, c0##nb##_3, \
           ah0_0, ah0_1, ah0_2, ah0_3, bB0, bB1); \
    MMA_OP(c1##na##_0, c1##na##_1, c1##na##_2, c1##na##_3, \
           ah1_0, ah1_1, ah1_2, ah1_3, bA0, bA1); \
    MMA_OP(c1##nb##_0, c1##nb##_1, c1##nb##_2, c1##nb##_3, \
           ah1_0, ah1_1, ah1_2, ah1_3, bB0, bB1); \
    MMA_OP(c0##na##_0, c0##na##_1, c0##na##_2, c0##na##_3, \
           al0_0, al0_1, al0_2, al0_3, bA0, bA1); \
    MMA_OP(c0##nb##_0, c0##nb##_1, c0##nb##_2, c0##nb##_3, \
           al0_0, al0_1, al0_2, al0_3, bB0, bB1); \
    MMA_OP(c1##na##_0, c1##na##_1, c1##na##_2, c1##na##_3, \
           al1_0, al1_1, al1_2, al1_3, bA0, bA1); \
    MMA_OP(c1##nb##_0, c1##nb##_1, c1##nb##_2, c1##nb##_3, \
           al1_0, al1_1, al1_2, al1_3, bB0, bB1); \
    MMA_OP(c0##na##_0, c0##na##_1, c0##na##_2, c0##na##_3, \
           ah0_0, ah0_1, ah0_2, ah0_3, lA0, lA1); \
    MMA_OP(c0##nb##_0, c0##nb##_1, c0##nb##_2, c0##nb##_3, \
           ah0_0, ah0_1, ah0_2, ah0_3, lB0, lB1); \
    MMA_OP(c1##na##_0, c1##na##_1, c1##na##_2, c1##na##_3, \
           ah1_0, ah1_1, ah1_2, ah1_3, lA0, lA1); \
    MMA_OP(c1##nb##_0, c1##nb##_1, c1##nb##_2, c1##nb##_3, \
           ah1_0, ah1_1, ah1_2, ah1_3, lB0, lB1); \
} while (0)

#define Q_K16(KX) do { \
    LDSM_OP(ah0_0, ah0_1, ah0_2, ah0_3, Ah + (ao0 ^ (KX))); \
    LDSM_OP(al0_0, al0_1, al0_2, al0_3, Al + (ao0 ^ (KX))); \
    LDSM_OP(ah1_0, ah1_1, ah1_2, ah1_3, Ah + (ao1 ^ (KX))); \
    LDSM_OP(al1_0, al1_1, al1_2, al1_3, Al + (ao1 ^ (KX))); \
    Q_NFP(0, 1, KX); Q_NFP(2, 3, KX); \
    Q_NFP(4, 5, KX); Q_NFP(6, 7, KX); \
} while (0)

#define STORE_Q(m, n) do { \
    int rr = wm * 32 + m * 16 + (lane >> 2); \
    int cc = wn * 64 + n * 8 + (lane & 3) * 2; \
    *(float2*)(Cp + (size_t)rr * ldc + cc) = make_float2(c##m##n##_0, c##m##n##_1); \
    *(float2*)(Cp + (size_t)(rr + 8) * ldc + cc) = make_float2(c##m##n##_2, c##m##n##_3); \
} while (0)

__global__ __launch_bounds__(512, 1)
void qkv3_kernel()
{
    extern __shared__ char smem[];
    uint32_t sbase = smem_to_u32(smem);

    const int mt = blockIdx.x, nt = blockIdx.y;
    const int m0 = mt * 128, n0 = nt * 256;
    const __nv_bfloat16* Ahi = g_Xhi + (size_t)m0 * DIM;
    const __nv_bfloat16* Alo = g_Xlo + (size_t)m0 * DIM;
    const __nv_bfloat16* Bhi = g_Wqkvt_hi + (size_t)n0 * DIM;
    const __nv_bfloat16* Blo = g_Wqkvt_lo + (size_t)n0 * DIM;
    float* Cp; int ldc;
    if (nt < 16)      { Cp = g_Q + (size_t)m0 * 4096 + n0;          ldc = 4096; }
    else if (nt < 20) { Cp = g_K + (size_t)m0 * 1024 + (n0 - 4096); ldc = 1024; }
    else              { Cp = g_V + (size_t)m0 * 1024 + (n0 - 5120); ldc = 1024; }

    const int tid  = threadIdx.x;
    const int lane = tid & 31;
    const int wid  = tid >> 5;     // 0..15
    const int wm   = wid >> 2;     // 0..3 : 32-row slab
    const int wn   = wid & 3;      // 0..3 : 64-col slab

    DECL_ACC(0,0); DECL_ACC(0,1); DECL_ACC(0,2); DECL_ACC(0,3);
    DECL_ACC(0,4); DECL_ACC(0,5); DECL_ACC(0,6); DECL_ACC(0,7);
    DECL_ACC(1,0); DECL_ACC(1,1); DECL_ACC(1,2); DECL_ACC(1,3);
    DECL_ACC(1,4); DECL_ACC(1,5); DECL_ACC(1,6); DECL_ACC(1,7);

    const int NT = DIM / 32;   // 128 iterations

    q_load_stage(sbase, 0, 0,  Ahi, Alo, Bhi, Blo, tid); CP_COMMIT();
    q_load_stage(sbase, 1, 32, Ahi, Alo, Bhi, Blo, tid); CP_COMMIT();

    // A offsets (kh16=0); kh16=1 is ^32 (flips swizzled ch bit1)
    const int arow0 = wm * 32 + ((lane >> 3) & 1) * 8 + (lane & 7);
    const uint32_t ao0 = qsw(arow0,      (lane >> 4));
    const uint32_t ao1 = qsw(arow0 + 16, (lane >> 4));
    // B offsets (kh16=0), x2 loads: lanes 0-15 address two n8 x k8 matrices
    const int brow = wn * 64 + (lane & 7);
    const int bch  = (lane >> 3) & 1;
    const uint32_t bo0 = qsw(brow,      bch);
    const uint32_t bo1 = qsw(brow + 8,  bch);
    const uint32_t bo2 = qsw(brow + 16, bch);
    const uint32_t bo3 = qsw(brow + 24, bch);
    const uint32_t bo4 = qsw(brow + 32, bch);
    const uint32_t bo5 = qsw(brow + 40, bch);
    const uint32_t bo6 = qsw(brow + 48, bch);
    const uint32_t bo7 = qsw(brow + 56, bch);

    for (int i = 0; i < NT; i++) {
        CP_WAIT(1);               // stage i resident
        __syncthreads();          // visibility + all reads of stage i-1 done
        int pf = i + 2;           // prefetch into buffer last read at i-1
        if (pf < NT)
            q_load_stage(sbase, pf % 3, pf * 32, Ahi, Alo, Bhi, Blo, tid);
        CP_COMMIT();

        uint32_t stb = sbase + (uint32_t)(i % 3) * QSTG;
        uint32_t Ah = stb, Al = stb + QBUF_A;
        uint32_t Bh = stb + 2 * QBUF_A, Bl = stb + 2 * QBUF_A + QBUF_B;

        uint32_t ah0_0, ah0_1, ah0_2, ah0_3, ah1_0, ah1_1, ah1_2, ah1_3;
        uint32_t al0_0, al0_1, al0_2, al0_3, al1_0, al1_1, al1_2, al1_3;

        Q_K16(0);    // k16 = 0
        Q_K16(32);   // k16 = 1
    }

    STORE_Q(0,0); STORE_Q(0,1); STORE_Q(0,2); STORE_Q(0,3);
    STORE_Q(0,4); STORE_Q(0,5); STORE_Q(0,6); STORE_Q(0,7);
    STORE_Q(1,0); STORE_Q(1,1); STORE_Q(1,2); STORE_Q(1,3);
    STORE_Q(1,4); STORE_Q(1,5); STORE_Q(1,6); STORE_Q(1,7);
}

// ===========================================================================
// Shared tiling for the out-projection (unchanged R13): CTA 128x128, BK=64,
// 512 threads / 16 warps, warp 32x32. smem row = 64 elems = 8 chunks.
// ===========================================================================
constexpr int GBUF_B    = 16384;               // 128 rows x 128B

__device__ __forceinline__ uint32_t gsw(int row, int ch) {
    return (uint32_t)(row * 128 + ((ch ^ (row & 7)) << 4));
}
__device__ __forceinline__ void load_buf(uint32_t dbase, const void* gp,
                                         int k0, int tid) {
    const __nv_bfloat16* g = (const __nv_bfloat16*)gp;
#pragma unroll
    for (int j = 0; j < 2; j++) {
        int c = tid * 2 + j;            // 0..1023
        int row = c >> 3, ch = c & 7;
        cp16(dbase + gsw(row, ch), g + (size_t)row * DIM + k0 + ch * 8);
    }
}

#define STORE_C(m, n) do { \
    int rr = wm * 32 + m * 16 + (lane >> 2); \
    int cc = wn * 32 + n * 8 + (lane & 3) * 2; \
    *(float2*)(Cp + (size_t)rr * ldc + cc) = make_float2(c##m##n##_0, c##m##n##_1); \
    *(float2*)(Cp + (size_t)(rr + 8) * ldc + cc) = make_float2(c##m##n##_2, c##m##n##_3); \
} while (0)

// ===========================================================================
// 1-term fp16 GEMM (output projection): C = Ch_hi @ Wot_h^T.
// 2 buffers/stage (A,B), 3 stages = 96KB. Single barrier/iter.
// ===========================================================================
constexpr int G2STG_B    = 2 * GBUF_B;          // 32KB
constexpr int GEMM2_SMEM = 3 * G2STG_B;         // 96KB

__device__ __forceinline__ void g_load_stage2(
    uint32_t sbase, int s, int k0,
    const __half* Ahi, const __half* Bhi, int tid)
{
    uint32_t stbase = sbase + (uint32_t)s * G2STG_B;
    load_buf(stbase,          Ahi, k0, tid);
    load_buf(stbase + GBUF_B, Bhi, k0, tid);
}

#define HT1(m, n, i0, i1) \
    MMAH_OP(c##m##n##_0, c##m##n##_1, c##m##n##_2, c##m##n##_3, \
            ah##m##_0, ah##m##_1, ah##m##_2, ah##m##_3, bh##n##_##i0, bh##n##_##i1)

#define GEMM2_K16(AOFF0, AOFF1, i0, i1) \
    LDSM_OP(ah0_0, ah0_1, ah0_2, ah0_3, Ah + (AOFF0)); \
    LDSM_OP(ah1_0, ah1_1, ah1_2, ah1_3, Ah + (AOFF1)); \
    HT1(0,0,i0,i1); HT1(0,1,i0,i1); HT1(0,2,i0,i1); HT1(0,3,i0,i1); \
    HT1(1,0,i0,i1); HT1(1,1,i0,i1); HT1(1,2,i0,i1); HT1(1,3,i0,i1)

#define LOAD_B2_KH2(kh2sel) \
    LDSM_OP(bh0_0, bh0_1, bh0_2, bh0_3, Bh + bo0_##kh2sel); \
    LDSM_OP(bh1_0, bh1_1, bh1_2, bh1_3, Bh + bo1_##kh2sel); \
    LDSM_OP(bh2_0, bh2_1, bh2_2, bh2_3, Bh + bo2_##kh2sel); \
    LDSM_OP(bh3_0, bh3_1, bh3_2, bh3_3, Bh + bo3_##kh2sel)

__global__ __launch_bounds__(512, 1)
void out2_kernel(float* __restrict__ out)
{
    extern __shared__ char smem[];
    uint32_t sbase = smem_to_u32(smem);

    const int m0 = (int)blockIdx.x * 128, n0 = (int)blockIdx.y * 128;
    const __half* Ahi = g_Ch_hi + (size_t)m0 * DIM;
    const __half* Bhi = g_Wot_h + (size_t)n0 * DIM;
    float* Cp = out + (size_t)m0 * DIM + n0;
    const int ldc = DIM;

    const int tid  = threadIdx.x;
    const int lane = tid & 31;
    const int wid  = tid >> 5;
    const int wm   = wid >> 2;
    const int wn   = wid & 3;

    DECL_ACC(0,0); DECL_ACC(0,1); DECL_ACC(0,2); DECL_ACC(0,3);
    DECL_ACC(1,0); DECL_ACC(1,1); DECL_ACC(1,2); DECL_ACC(1,3);

    const int NT = DIM / 64;

    g_load_stage2(sbase, 0, 0,  Ahi, Bhi, tid); CP_COMMIT();
    g_load_stage2(sbase, 1, 64, Ahi, Bhi, tid); CP_COMMIT();

    const int ar0 = wm * 32 + ((lane >> 3) & 1) * 8 + (lane & 7);
    const int ar1 = ar0 + 16;
    const int ln16 = lane >> 4;
    const uint32_t ao0_0 = gsw(ar0, 0 + ln16), ao0_1 = gsw(ar0, 2 + ln16);
    const uint32_t ao0_2 = gsw(ar0, 4 + ln16), ao0_3 = gsw(ar0, 6 + ln16);
    const uint32_t ao1_0 = gsw(ar1, 0 + ln16), ao1_1 = gsw(ar1, 2 + ln16);
    const uint32_t ao1_2 = gsw(ar1, 4 + ln16), ao1_3 = gsw(ar1, 6 + ln16);
    const int ln8 = lane >> 3;
    const uint32_t bo0_0 = gsw(wn*32 + 0  + (lane&7), ln8);
    const uint32_t bo1_0 = gsw(wn*32 + 8  + (lane&7), ln8);
    const uint32_t bo2_0 = gsw(wn*32 + 16 + (lane&7), ln8);
    const uint32_t bo3_0 = gsw(wn*32 + 24 + (lane&7), ln8);
    const uint32_t bo0_1 = gsw(wn*32 + 0  + (lane&7), 4 + ln8);
    const uint32_t bo1_1 = gsw(wn*32 + 8  + (lane&7), 4 + ln8);
    const uint32_t bo2_1 = gsw(wn*32 + 16 + (lane&7), 4 + ln8);
    const uint32_t bo3_1 = gsw(wn*32 + 24 + (lane&7), 4 + ln8);

    for (int i = 0; i < NT; i++) {
        CP_WAIT(1);
        __syncthreads();
        int pf = i + 2;
        if (pf < NT)
            g_load_stage2(sbase, pf % 3, pf * 64, Ahi, Bhi, tid);
        CP_COMMIT();

        uint32_t stb = sbase + (uint32_t)(i % 3) * G2STG_B;
        uint32_t Ah = stb, Bh = stb + GBUF_B;

        DECL_F(bh, 0); DECL_F(bh, 1); DECL_F(bh, 2); DECL_F(bh, 3);
        uint32_t ah0_0, ah0_1, ah0_2, ah0_3, ah1_0, ah1_1, ah1_2, ah1_3;

        LOAD_B2_KH2(0);
        GEMM2_K16(ao0_0, ao1_0, 0, 1);
        GEMM2_K16(ao0_1, ao1_1, 2, 3);
        LOAD_B2_KH2(1);
        GEMM2_K16(ao0_2, ao1_2, 0, 1);
        GEMM2_K16(ao0_3, ao1_3, 2, 3);
    }

    STORE_C(0,0); STORE_C(0,1); STORE_C(0,2); STORE_C(0,3);
    STORE_C(1,0); STORE_C(1,1); STORE_C(1,2); STORE_C(1,3);
}

// ===========================================================================
// Fast exp on the FMA pipe
// ===========================================================================
__device__ __forceinline__ float fexp(float x) {
    float y = x * 1.4426950408889634f;
    y = fmaxf(y, -125.0f);
    float fl = floorf(y);
    float t = y - fl;
    float r = 1.5403530e-4f;
    r = fmaf(r, t, 1.3333558e-3f);
    r = fmaf(r, t, 9.6181291e-3f);
    r = fmaf(r, t, 5.5504109e-2f);
    r = fmaf(r, t, 2.4022651e-1f);
    r = fmaf(r, t, 6.9314718e-1f);
    r = fmaf(r, t, 1.0f);
    float s = __int_as_float(((int)fl + 127) << 23);
    return r * s;
}

// ===========================================================================
// RoPE + scale + split: fp32 Q/K/V -> split bf16 (Q scaled by 1/sqrt(HD))
// ===========================================================================
__global__ void ropesplit_kernel(const int* __restrict__ pos)
{
    int idx = blockIdx.x * blockDim.x + threadIdx.x;
    const int NQP = SEQ * NH * 64;
    const int NKP = SEQ * NKV * 64;
    const int NVP = SEQ * NKV * 64;
    if (idx >= NQP + NKP + NVP) return;

    if (idx < NQP) {
        int i = idx & 63, h = (idx >> 6) & 31, s = idx >> 11;
        size_t o = (size_t)s * (NH * HDIM) + h * HDIM + i;
        float x1 = g_Q[o], x2 = g_Q[o + 64];
        float p = (float)pos[s];
        float freq = (float)exp2(-(double)i * 0.31143075889569021);
        float sn, cs; sincosf(p * freq, &sn, &cs);
        const float sc = 0.08838834764831845f;
        float y1 = (x1 * cs - x2 * sn) * sc;
        float y2 = (x1 * sn + x2 * cs) * sc;
        __nv_bfloat16 hh, ll;
        split1(y1, hh, ll); g_Qhi[o] = hh;      g_Qlo[o] = ll;
        split1(y2, hh, ll); g_Qhi[o + 64] = hh; g_Qlo[o + 64] = ll;
    } else if (idx < NQP + NKP) {
        int t = idx - NQP;
        int i = t & 63, g = (t >> 6) & 7, s = t >> 9;
        size_t o = (size_t)s * (NKV * HDIM) + g * HDIM + i;
        float x1 = g_K[o], x2 = g_K[o + 64];
        float p = (float)pos[s];
        float freq = (float)exp2(-(double)i * 0.31143075889569021);
        float sn, cs; sincosf(p * freq, &sn, &cs);
        float y1 = x1 * cs - x2 * sn;
        float y2 = x1 * sn + x2 * cs;
        __nv_bfloat16 hh, ll;
        split1(y1, hh, ll); g_Khi[o] = hh;      g_Klo[o] = ll;
        split1(y2, hh, ll); g_Khi[o + 64] = hh; g_Klo[o + 64] = ll;
    } else {
        int t = idx - NQP - NKP;
        int i = t & 63, g = (t >> 6) & 7, s = t >> 9;
        size_t o = (size_t)s * (NKV * HDIM) + g * HDIM + i;
        __nv_bfloat16 hh, ll;
        split1(g_V[o], hh, ll);      g_Vhi[o] = hh;      g_Vlo[o] = ll;
        split1(g_V[o + 64], hh, ll); g_Vhi[o + 64] = hh; g_Vlo[o + 64] = ll;
    }
}

// ===========================================================================
// HMMA flash attention (R13-proven; single barrier per kt; fp16 context out)
// ===========================================================================
constexpr int AQ_B     = 32768;
constexpr int AKV_B    = 16384;
constexpr int AST_B    = 4 * AKV_B;
constexpr int AMSK_OFF = 2 * AQ_B + 2 * AST_B;
constexpr int ATTN_SMEM = AMSK_OFF + 768;      // 2 x 64-float mask slots

__device__ __forceinline__ uint32_t asw(int row, int ch) {
    return (uint32_t)(row * 256 + ((ch ^ (row & 7)) << 4));
}
__device__ __forceinline__ uint32_t a_addr(uint32_t base, int m0, int cb, int lane) {
    int row = m0 + ((lane >> 3) & 1) * 8 + (lane & 7);
    return base + asw(row, cb + (lane >> 4));
}
__device__ __forceinline__ uint32_t b_addr(uint32_t base, int n0, int cb, int lane) {
    int row = n0 + (lane & 7);
    return base + asw(row, cb + (lane >> 3));
}
__device__ __forceinline__ uint32_t v_addr(uint32_t base, int t, int nfp, int lane) {
    int g = lane >> 3;
    int row = t * 16 + (g & 1) * 8 + (lane & 7);
    return base + asw(row, nfp * 2 + (g >> 1));
}

__device__ __forceinline__ void load_q_buf(uint32_t dst, const __nv_bfloat16* g,
                                           int q0, int h, int tid) {
#pragma unroll
    for (int j = 0; j < 8; j++) {
        int c = tid * 8 + j;
        int row = c >> 4, ch = c & 15;
        cp16(dst + asw(row, ch),
             g + (size_t)(q0 + row) * (NH * HDIM) + h * HDIM + ch * 8);
    }
}
__device__ __forceinline__ void load_kv_arr(uint32_t dst, const __nv_bfloat16* g,
                                            int s0, int gkv, int tid) {
#pragma unroll
    for (int j = 0; j < 4; j++) {
        int c = tid * 4 + j;
        int row = c >> 4, ch = c & 15;
        cp16(dst + asw(row, ch),
             g + (size_t)(s0 + row) * (NKV * HDIM) + gkv * HDIM + ch * 8);
    }
}

#define DECL_S(n) float s##n##_0, s##n##_1, s##n##_2, s##n##_3
#define ZERO_S(n) s##n##_0 = 0.f; s##n##_1 = 0.f; s##n##_2 = 0.f; s##n##_3 = 0.f
#define DECL_O(n) float o##n##_0 = 0.f, o##n##_1 = 0.f, o##n##_2 = 0.f, o##n##_3 = 0.f

#define SMMA_T(nf, A0,A1,A2,A3, B0,B1) \
    MMA_OP(s##nf##_0, s##nf##_1, s##nf##_2, s##nf##_3, A0,A1,A2,A3, B0,B1)

#define S_NF2(na, nb) do { \
    uint32_t kA0,kA1,kA2,kA3, lA0,lA1,lA2,lA3; \
    uint32_t kB0,kB1,kB2,kB3, lB0,lB1,lB2,lB3; \
    LDSM_OP(kA0,kA1,kA2,kA3, b_addr(KhB, (na)*8, ks2*4, lane)); \
    LDSM_OP(kB0,kB1,kB2,kB3, b_addr(KhB, (nb)*8, ks2*4, lane)); \
    LDSM_OP(lA0,lA1,lA2,lA3, b_addr(KlB, (na)*8, ks2*4, lane)); \
    LDSM_OP(lB0,lB1,lB2,lB3, b_addr(KlB, (nb)*8, ks2*4, lane)); \
    SMMA_T(na, qh0,qh1,qh2,qh3, kA0,kA1); \
    SMMA_T(nb, qh0,qh1,qh2,qh3, kB0,kB1); \
    SMMA_T(na, ql0,ql1,ql2,ql3, kA0,kA1); \
    SMMA_T(nb, ql0,ql1,ql2,ql3, kB0,kB1); \
    SMMA_T(na, qh0,qh1,qh2,qh3, lA0,lA1); \
    SMMA_T(nb, qh0,qh1,qh2,qh3, lB0,lB1); \
    SMMA_T(na, qh4,qh5,qh6,qh7, kA2,kA3); \
    SMMA_T(nb, qh4,qh5,qh6,qh7, kB2,kB3); \
    SMMA_T(na, ql4,ql5,ql6,ql7, kA2,kA3); \
    SMMA_T(nb, ql4,ql5,ql6,ql7, kB2,kB3); \
    SMMA_T(na, qh4,qh5,qh6,qh7, lA2,lA3); \
    SMMA_T(nb, qh4,qh5,qh6,qh7, lB2,lB3); \
} while (0)

#define MASK_NF(nf) do { \
    int lc = (nf) * 8 + ((lane & 3) << 1); \
    float mA = mskp[lc], mB = mskp[lc + 1]; \
    int cg = k0 + lc; \
    s##nf##_0 += (mA > 0.f && (!cz || cg     <= rg0)) ? 0.f : -1e30f; \
    s##nf##_1 += (mB > 0.f && (!cz || cg + 1 <= rg0)) ? 0.f : -1e30f; \
    s##nf##_2 += (mA > 0.f && (!cz || cg     <= rg1)) ? 0.f : -1e30f; \
    s##nf##_3 += (mB > 0.f && (!cz || cg + 1 <= rg1)) ? 0.f : -1e30f; \
} while (0)

#define MAX_NF(nf) \
    mx0 = fmaxf(mx0, fmaxf(s##nf##_0, s##nf##_1)); \
    mx1 = fmaxf(mx1, fmaxf(s##nf##_2, s##nf##_3))

#define EXP_NF(nf) \
    s##nf##_0 = fexp(s##nf##_0 - mn0); sum0 += s##nf##_0; \
    s##nf##_1 = fexp(s##nf##_1 - mn0); sum0 += s##nf##_1; \
    s##nf##_2 = fexp(s##nf##_2 - mn1); sum1 += s##nf##_2; \
    s##nf##_3 = fexp(s##nf##_3 - mn1); sum1 += s##nf##_3

#define SCALE_O(n) \
    o##n##_0 *= al0; o##n##_1 *= al0; o##n##_2 *= al1; o##n##_3 *= al1

#define OMMA_T(on, A0,A1,A2,A3, B0,B1) \
    MMA_OP(o##on##_0, o##on##_1, o##on##_2, o##on##_3, A0,A1,A2,A3, B0,B1)

#define PV_NFP(tt, nfp, oA, oB) do { \
    uint32_t vh0,vh1,vh2,vh3, vl0,vl1,vl2,vl3; \
    LDSMT_OP(vh0,vh1,vh2,vh3, v_addr(VhB, tt, nfp, lane)); \
    LDSMT_OP(vl0,vl1,vl2,vl3, v_addr(VlB, tt, nfp, lane)); \
    OMMA_T(oA, pa0,pa1,pa2,pa3, vh0,vh1); \
    OMMA_T(oB, pa0,pa1,pa2,pa3, vh2,vh3); \
    OMMA_T(oA, la0,la1,la2,la3, vh0,vh1); \
    OMMA_T(oB, la0,la1,la2,la3, vh2,vh3); \
    OMMA_T(oA, pa0,pa1,pa2,pa3, vl0,vl1); \
    OMMA_T(oB, pa0,pa1,pa2,pa3, vl2,vl3); \
} while (0)

#define PVT(e, f, tt) do { \
    uint32_t pa0,pa1,pa2,pa3, la0,la1,la2,la3; \
    packsplit(s##e##_0, s##e##_1, pa0, la0); \
    packsplit(s##e##_2, s##e##_3, pa1, la1); \
    packsplit(s##f##_0, s##f##_1, pa2, la2); \
    packsplit(s##f##_2, s##f##_3, pa3, la3); \
    PV_NFP(tt, 0, 0, 1);  PV_NFP(tt, 1, 2, 3); \
    PV_NFP(tt, 2, 4, 5);  PV_NFP(tt, 3, 6, 7); \
    PV_NFP(tt, 4, 8, 9);  PV_NFP(tt, 5, 10, 11); \
    PV_NFP(tt, 6, 12, 13); PV_NFP(tt, 7, 14, 15); \
} while (0)

#define EPI_O(n) do { \
    __half2 hv = __floats2half2_rn(o##n##_0 * il0, o##n##_1 * il0); \
    *(__half2*)(g_Ch_hi + ro0 + (n) * 8) = hv; \
    hv = __floats2half2_rn(o##n##_2 * il1, o##n##_3 * il1); \
    *(__half2*)(g_Ch_hi + ro1 + (n) * 8) = hv; \
} while (0)

__global__ __launch_bounds__(256, 1)
void attn_mma_kernel(const float* __restrict__ amask)
{
    extern __shared__ char smem[];
    uint32_t sbase = smem_to_u32(smem);
    float* msk = (float*)(smem + AMSK_OFF);   // 2 slots x 64

    const int h    = blockIdx.x;
    const int qt   = (int)gridDim.y - 1 - (int)blockIdx.y;
    const int gkv  = h >> 2;
    const int tid  = threadIdx.x;
    const int lane = tid & 31;
    const int wid  = tid >> 5;
    const int q0   = qt * 128;

    const uint32_t QhB = sbase, QlB = sbase + AQ_B;

    load_q_buf(QhB, g_Qhi, q0, h, tid);
    load_q_buf(QlB, g_Qlo, q0, h, tid);
    {
        uint32_t st = sbase + 2 * AQ_B;
        load_kv_arr(st,             g_Khi, 0, gkv, tid);
        load_kv_arr(st + AKV_B,     g_Klo, 0, gkv, tid);
        load_kv_arr(st + 2 * AKV_B, g_Vhi, 0, gkv, tid);
        load_kv_arr(st + 3 * AKV_B, g_Vlo, 0, gkv, tid);
    }
    CP_COMMIT();

    DECL_O(0);  DECL_O(1);  DECL_O(2);  DECL_O(3);
    DECL_O(4);  DECL_O(5);  DECL_O(6);  DECL_O(7);
    DECL_O(8);  DECL_O(9);  DECL_O(10); DECL_O(11);
    DECL_O(12); DECL_O(13); DECL_O(14); DECL_O(15);
    float m0 = -1e30f, m1 = -1e30f, l0 = 0.f, l1 = 0.f;

    const int rg0 = q0 + wid * 16 + (lane >> 2);
    const int rg1 = rg0 + 8;
    const int ktmax = 2 * qt + 1;

    for (int kt = 0; kt <= ktmax; kt++) {
        const int k0 = kt * 64;
        const uint32_t stg = sbase + 2 * AQ_B + (uint32_t)(kt & 1) * AST_B;
        float* mskp = msk + (kt & 1) * 64;

        if (tid < 64) mskp[tid] = amask[k0 + tid];
        CP_WAIT(0);               // stage kt (and Q on kt==0) resident
        __syncthreads();          // visibility + all reads of stage kt-1 done

        if (kt < ktmax) {
            uint32_t nst = sbase + 2 * AQ_B + (uint32_t)((kt + 1) & 1) * AST_B;
            int ns = (kt + 1) * 64;
            load_kv_arr(nst,             g_Khi, ns, gkv, tid);
            load_kv_arr(nst + AKV_B,     g_Klo, ns, gkv, tid);
            load_kv_arr(nst + 2 * AKV_B, g_Vhi, ns, gkv, tid);
            load_kv_arr(nst + 3 * AKV_B, g_Vlo, ns, gkv, tid);
            CP_COMMIT();
        }

        const uint32_t KhB = stg, KlB = stg + AKV_B;
        const uint32_t VhB = stg + 2 * AKV_B, VlB = stg + 3 * AKV_B;
        const bool cz = (kt >= 2 * qt);

        DECL_S(0); DECL_S(1); DECL_S(2); DECL_S(3);
        DECL_S(4); DECL_S(5); DECL_S(6); DECL_S(7);
        ZERO_S(0); ZERO_S(1); ZERO_S(2); ZERO_S(3);
        ZERO_S(4); ZERO_S(5); ZERO_S(6); ZERO_S(7);

#pragma unroll
        for (int ks2 = 0; ks2 < 4; ks2++) {
            uint32_t qh0, qh1, qh2, qh3, qh4, qh5, qh6, qh7;
            uint32_t ql0, ql1, ql2, ql3, ql4, ql5, ql6, ql7;
            LDSM_OP(qh0, qh1, qh2, qh3, a_addr(QhB, wid * 16, ks2 * 4, lane));
            LDSM_OP(qh4, qh5, qh6, qh7, a_addr(QhB, wid * 16, ks2 * 4 + 2, lane));
            LDSM_OP(ql0, ql1, ql2, ql3, a_addr(QlB, wid * 16, ks2 * 4, lane));
            LDSM_OP(ql4, ql5, ql6, ql7, a_addr(QlB, wid * 16, ks2 * 4 + 2, lane));
            S_NF2(0, 1); S_NF2(2, 3); S_NF2(4, 5); S_NF2(6, 7);
        }

        MASK_NF(0); MASK_NF(1); MASK_NF(2); MASK_NF(3);
        MASK_NF(4); MASK_NF(5); MASK_NF(6); MASK_NF(7);

        float mx0 = -1e30f, mx1 = -1e30f;
        MAX_NF(0); MAX_NF(1); MAX_NF(2); MAX_NF(3);
        MAX_NF(4); MAX_NF(5); MAX_NF(6); MAX_NF(7);
        mx0 = fmaxf(mx0, __shfl_xor_sync(0xffffffffu, mx0, 1, 4));
        mx0 = fmaxf(mx0, __shfl_xor_sync(0xffffffffu, mx0, 2, 4));
        mx1 = fmaxf(mx1, __shfl_xor_sync(0xffffffffu, mx1, 1, 4));
        mx1 = fmaxf(mx1, __shfl_xor_sync(0xffffffffu, mx1, 2, 4));

        float mn0 = fmaxf(m0, mx0), mn1 = fmaxf(m1, mx1);
        float al0 = fexp(m0 - mn0), al1 = fexp(m1 - mn1);
        m0 = mn0; m1 = mn1;

        float sum0 = 0.f, sum1 = 0.f;
        EXP_NF(0); EXP_NF(1); EXP_NF(2); EXP_NF(3);
        EXP_NF(4); EXP_NF(5); EXP_NF(6); EXP_NF(7);
        sum0 += __shfl_xor_sync(0xffffffffu, sum0, 1, 4);
        sum0 += __shfl_xor_sync(0xffffffffu, sum0, 2, 4);
        sum1 += __shfl_xor_sync(0xffffffffu, sum1, 1, 4);
        sum1 += __shfl_xor_sync(0xffffffffu, sum1, 2, 4);
        l0 = l0 * al0 + sum0;
        l1 = l1 * al1 + sum1;

        SCALE_O(0);  SCALE_O(1);  SCALE_O(2);  SCALE_O(3);
        SCALE_O(4);  SCALE_O(5);  SCALE_O(6);  SCALE_O(7);
        SCALE_O(8);  SCALE_O(9);  SCALE_O(10); SCALE_O(11);
        SCALE_O(12); SCALE_O(13); SCALE_O(14); SCALE_O(15);

        PVT(0, 1, 0); PVT(2, 3, 1); PVT(4, 5, 2); PVT(6, 7, 3);
    }

    const float il0 = 1.0f / l0, il1 = 1.0f / l1;
    const size_t ro0 = (size_t)rg0 * DIM + h * HDIM + ((lane & 3) << 1);
    const size_t ro1 = ro0 + (size_t)8 * DIM;
    EPI_O(0);  EPI_O(1);  EPI_O(2);  EPI_O(3);
    EPI_O(4);  EPI_O(5);  EPI_O(6);  EPI_O(7);
    EPI_O(8);  EPI_O(9);  EPI_O(10); EPI_O(11);
    EPI_O(12); EPI_O(13); EPI_O(14); EPI_O(15);
}

// ===========================================================================
extern "C" void kernel_launch(void* const* d_in, const int* in_sizes, int n_in,
                              void* d_out, int out_size)
{
    const float* X   = (const float*)d_in[0];
    const float* am  = (const float*)d_in[1];
    const int*   pos = (const int*)  d_in[2];
    const float* wq  = (const float*)d_in[3];
    const float* wk  = (const float*)d_in[4];
    const float* wv  = (const float*)d_in[5];
    const float* wo  = (const float*)d_in[6];
    float* out = (float*)d_out;

    (void)in_sizes; (void)n_in; (void)out_size;

    // 1. Split conversions
    xsplit_kernel<<<(SEQ * DIM / 4 + 255) / 256, 256>>>(X, SEQ * DIM / 4);
    wsplit_t_kernel<<<dim3(4096 / 32, 4096 / 32), 256>>>(wq, 4096, 0);
    wsplit_t_kernel<<<dim3(1024 / 32, 4096 / 32), 256>>>(wk, 1024, 4096);
    wsplit_t_kernel<<<dim3(1024 / 32, 4096 / 32), 256>>>(wv, 1024, 5120);
    wsplit_wo_kernel<<<dim3(4096 / 32, 4096 / 32), 256>>>(wo);

    // 2. QKV projection (HMMA split-bf16 3-term, CTA 128x256 warp 32x64)
    cudaFuncSetAttribute((const void*)qkv3_kernel,
                         cudaFuncAttributeMaxDynamicSharedMemorySize, QKV_SMEM);
    qkv3_kernel<<<dim3(16, 24), 512, QKV_SMEM>>>();

    // 3. RoPE + scale + split-bf16 conversion of Q/K/V
    int tot = SEQ * NH * 64 + 2 * SEQ * NKV * 64;
    ropesplit_kernel<<<(tot + 255) / 256, 256>>>(pos);

    // 4. HMMA flash attention (single barrier/kt; fp16 context out)
    cudaFuncSetAttribute((const void*)attn_mma_kernel,
                         cudaFuncAttributeMaxDynamicSharedMemorySize, ATTN_SMEM);
    attn_mma_kernel<<<dim3(NH, SEQ / 128), 256, ATTN_SMEM>>>(am);

    // 5. Output projection (pure fp16 1-term HMMA)
    cudaFuncSetAttribute((const void*)out2_kernel,
                         cudaFuncAttributeMaxDynamicSharedMemorySize, GEMM2_SMEM);
    out2_kernel<<<dim3(16, 32), 512, GEMM2_SMEM>>>(out);
}

// round 16
// speedup vs baseline: 1.0025x; 1.0025x over previous
#include <cuda_runtime.h>
#include <cuda_bf16.h>
#include <cuda_fp16.h>
#include <math.h>
#include <cstdint>

// Problem shape constants
constexpr int SEQ  = 2048;
constexpr int DIM  = 4096;
constexpr int NH   = 32;
constexpr int NKV  = 8;
constexpr int HDIM = 128;

// Scratch (device globals: allocation-free rule)
__device__ float g_Q[SEQ * NH * HDIM];     // fp32 QKV-GEMM outputs
__device__ float g_K[SEQ * NKV * HDIM];
__device__ float g_V[SEQ * NKV * HDIM];

// Split-bf16 operands (16B-aligned for cp.async)
__device__ __align__(256) __nv_bfloat16 g_Xhi[SEQ * DIM];
__device__ __align__(256) __nv_bfloat16 g_Xlo[SEQ * DIM];
__device__ __align__(256) __nv_bfloat16 g_Wqkvt_hi[6144 * DIM];
__device__ __align__(256) __nv_bfloat16 g_Wqkvt_lo[6144 * DIM];
// fp16 operands for the 1-term output projection
__device__ __align__(256) __half g_Wot_h[DIM * DIM];   // [N=4096][K=4096] = Wo^T, fp16
__device__ __align__(256) __half g_Ch_hi[SEQ * DIM];   // attention out, fp16
// Split bf16 Q/K/V for HMMA attention (RoPE + scale folded into Q)
__device__ __align__(256) __nv_bfloat16 g_Qhi[SEQ * NH * HDIM];
__device__ __align__(256) __nv_bfloat16 g_Qlo[SEQ * NH * HDIM];
__device__ __align__(256) __nv_bfloat16 g_Khi[SEQ * NKV * HDIM];
__device__ __align__(256) __nv_bfloat16 g_Klo[SEQ * NKV * HDIM];
__device__ __align__(256) __nv_bfloat16 g_Vhi[SEQ * NKV * HDIM];
__device__ __align__(256) __nv_bfloat16 g_Vlo[SEQ * NKV * HDIM];

// ===========================================================================
// PTX helpers
// ===========================================================================
__device__ __forceinline__ uint32_t smem_to_u32(const void* smem_ptr) {
    uint32_t addr;
    asm("{ .reg .u64 tmp; cvta.to.shared.u64 tmp, %1; cvt.u32.u64 %0, tmp; }"
        : "=r"(addr) : "l"(smem_ptr));
    return addr;
}
__device__ __forceinline__ void cp16(uint32_t dst, const void* src) {
    asm volatile("cp.async.cg.shared.global [%0], [%1], 16;\n" :: "r"(dst), "l"(src));
}
#define CP_COMMIT() asm volatile("cp.async.commit_group;\n" ::: "memory")
#define CP_WAIT(n)  asm volatile("cp.async.wait_group %0;\n" :: "n"(n) : "memory")

#define LDSM_OP(r0, r1, r2, r3, addr) \
    asm volatile("ldmatrix.sync.aligned.m8n8.x4.shared.b16 {%0,%1,%2,%3}, [%4];" \
        : "=r"(r0), "=r"(r1), "=r"(r2), "=r"(r3) : "r"(addr))
#define LDSM2_OP(r0, r1, addr) \
    asm volatile("ldmatrix.sync.aligned.m8n8.x2.shared.b16 {%0,%1}, [%2];" \
        : "=r"(r0), "=r"(r1) : "r"(addr))
#define LDSMT_OP(r0, r1, r2, r3, addr) \
    asm volatile("ldmatrix.sync.aligned.m8n8.x4.trans.shared.b16 {%0,%1,%2,%3}, [%4];" \
        : "=r"(r0), "=r"(r1), "=r"(r2), "=r"(r3) : "r"(addr))

#define MMA_OP(d0, d1, d2, d3, A0, A1, A2, A3, B0, B1) \
    asm volatile("mma.sync.aligned.m16n8k16.row.col.f32.bf16.bf16.f32 " \
        "{%0,%1,%2,%3}, {%4,%5,%6,%7}, {%8,%9}, {%0,%1,%2,%3};" \
        : "+f"(d0), "+f"(d1), "+f"(d2), "+f"(d3) \
        : "r"(A0), "r"(A1), "r"(A2), "r"(A3), "r"(B0), "r"(B1))

#define MMAH_OP(d0, d1, d2, d3, A0, A1, A2, A3, B0, B1) \
    asm volatile("mma.sync.aligned.m16n8k16.row.col.f32.f16.f16.f32 " \
        "{%0,%1,%2,%3}, {%4,%5,%6,%7}, {%8,%9}, {%0,%1,%2,%3};" \
        : "+f"(d0), "+f"(d1), "+f"(d2), "+f"(d3) \
        : "r"(A0), "r"(A1), "r"(A2), "r"(A3), "r"(B0), "r"(B1))

// ===========================================================================
// Split conversions
// ===========================================================================
__device__ __forceinline__ void split1(float x, __nv_bfloat16& h, __nv_bfloat16& l) {
    h = __float2bfloat16(x);
    l = __float2bfloat16(x - __bfloat162float(h));
}
__device__ __forceinline__ void packsplit(float x, float y, uint32_t& hi, uint32_t& lo) {
    uint32_t hx = (uint32_t)__bfloat16_as_ushort(__float2bfloat16(x));
    uint32_t hy = (uint32_t)__bfloat16_as_ushort(__float2bfloat16(y));
    float rx = x - __uint_as_float(hx << 16);
    float ry = y - __uint_as_float(hy << 16);
    uint32_t lx = (uint32_t)__bfloat16_as_ushort(__float2bfloat16(rx));
    uint32_t ly = (uint32_t)__bfloat16_as_ushort(__float2bfloat16(ry));
    hi = (hy << 16) | hx;
    lo = (ly << 16) | lx;
}

__global__ void xsplit_kernel(const float* __restrict__ X, int total4) {
    int idx = blockIdx.x * blockDim.x + threadIdx.x;
    if (idx >= total4) return;
    float4 v = ((const float4*)X)[idx];
    __nv_bfloat16 h0, h1, h2, h3, l0, l1, l2, l3;
    split1(v.x, h0, l0); split1(v.y, h1, l1);
    split1(v.z, h2, l2); split1(v.w, h3, l3);
    __nv_bfloat162* H2 = (__nv_bfloat162*)(g_Xhi + (size_t)idx * 4);
    __nv_bfloat162* L2 = (__nv_bfloat162*)(g_Xlo + (size_t)idx * 4);
    H2[0] = __nv_bfloat162(h0, h1); H2[1] = __nv_bfloat162(h2, h3);
    L2[0] = __nv_bfloat162(l0, l1); L2[1] = __nv_bfloat162(l2, l3);
}

// QKV weights: transpose + bf16 hi/lo split
__global__ void wsplit_t_kernel(const float* __restrict__ W, int N, int dst_row_off) {
    __shared__ float s[32][33];
    int n0 = blockIdx.x * 32, k0 = blockIdx.y * 32;
    int lx = threadIdx.x & 31, ly = threadIdx.x >> 5;
#pragma unroll
    for (int r = 0; r < 4; r++) {
        int row = ly + r * 8;
        s[row][lx] = W[(size_t)(k0 + row) * N + n0 + lx];
    }
    __syncthreads();
#pragma unroll
    for (int r = 0; r < 4; r++) {
        int nrow = ly + r * 8;
        float x = s[lx][nrow];
        __nv_bfloat16 h, l; split1(x, h, l);
        size_t o = (size_t)(dst_row_off + n0 + nrow) * DIM + k0 + lx;
        g_Wqkvt_hi[o] = h; g_Wqkvt_lo[o] = l;
    }
}

// Wo: transpose + fp16 (1-term out-projection)
__global__ void wsplit_wo_kernel(const float* __restrict__ W) {
    __shared__ float s[32][33];
    int n0 = blockIdx.x * 32, k0 = blockIdx.y * 32;
    int lx = threadIdx.x & 31, ly = threadIdx.x >> 5;
#pragma unroll
    for (int r = 0; r < 4; r++) {
        int row = ly + r * 8;
        s[row][lx] = W[(size_t)(k0 + row) * DIM + n0 + lx];
    }
    __syncthreads();
#pragma unroll
    for (int r = 0; r < 4; r++) {
        int nrow = ly + r * 8;
        g_Wot_h[(size_t)(n0 + nrow) * DIM + k0 + lx] = __float2half_rn(s[lx][nrow]);
    }
}

// ===========================================================================
// QKV GEMM: CTA 128x256, BK=32, 512 threads / 16 warps (4m x 4n), warp tile
// 32x64. 3-term split-bf16. A frags (x4) reused across 8 n-frags; B loaded
// as x2 (halved register residency). smem row = 32 bf16 = 4 x 16B chunks,
// swizzle ch ^= (row>>1)&3. Flipping k16 flips exactly offset bit 5 (^32).
// 3 stages x 48KB = 144KB, single barrier per iteration.
// ===========================================================================
constexpr int QBUF_A   = 8192;                 // 128 rows x 64B
constexpr int QBUF_B   = 16384;                // 256 rows x 64B
constexpr int QSTG     = 2 * QBUF_A + 2 * QBUF_B;  // 48KB
constexpr int QKV_SMEM = 3 * QSTG;                 // 144KB

__device__ __forceinline__ uint32_t qsw(int row, int ch) {
    return (uint32_t)(row * 64 + ((ch ^ ((row >> 1) & 3)) << 4));
}
__device__ __forceinline__ void q_load_a(uint32_t dbase, const __nv_bfloat16* g,
                                         int k0, int tid) {
    int row = tid >> 2, ch = tid & 3;
    cp16(dbase + qsw(row, ch), g + (size_t)row * DIM + k0 + ch * 8);
}
__device__ __forceinline__ void q_load_b(uint32_t dbase, const __nv_bfloat16* g,
                                         int k0, int tid) {
#pragma unroll
    for (int j = 0; j < 2; j++) {
        int c = tid * 2 + j;            // 0..1023
        int row = c >> 2, ch = c & 3;
        cp16(dbase + qsw(row, ch), g + (size_t)row * DIM + k0 + ch * 8);
    }
}
__device__ __forceinline__ void q_load_stage(
    uint32_t sbase, int s, int k0,
    const __nv_bfloat16* Ahi, const __nv_bfloat16* Alo,
    const __nv_bfloat16* Bhi, const __nv_bfloat16* Blo, int tid)
{
    uint32_t st = sbase + (uint32_t)s * QSTG;
    q_load_a(st,                     Ahi, k0, tid);
    q_load_a(st + QBUF_A,            Alo, k0, tid);
    q_load_b(st + 2 * QBUF_A,        Bhi, k0, tid);
    q_load_b(st + 2 * QBUF_A + QBUF_B, Blo, k0, tid);
}

#define DECL_ACC(m, n) \
    float c##m##n##_0 = 0.f, c##m##n##_1 = 0.f, c##m##n##_2 = 0.f, c##m##n##_3 = 0.f
#define DECL_F(p, n) uint32_t p##n##_0, p##n##_1, p##n##_2, p##n##_3

// One nf-pair at one k16: 4 x2 B loads + 12 term-grouped MMAs (dep gap 3)
#define Q_NFP(na, nb, KX) do { \
    uint32_t bA0, bA1, bB0, bB1, lA0, lA1, lB0, lB1; \
    LDSM2_OP(bA0, bA1, Bh + (bo##na ^ (KX))); \
    LDSM2_OP(bB0, bB1, Bh + (bo##nb ^ (KX))); \
    LDSM2_OP(lA0, lA1, Bl + (bo##na ^ (KX))); \
    LDSM2_OP(lB0, lB1, Bl + (bo##nb ^ (KX))); \
    MMA_OP(c0##na##_0, c0##na##_1, c0##na##_2, c0##na##_3, \
           ah0_0, ah0_1, ah0_2, ah0_3, bA0, bA1); \
    MMA_OP(c0##nb##_0, c0##nb##_1, c0##nb##_2, c0##nb##_3, \
           ah0_0, ah0_1, ah0_2, ah0_3, bB0, bB1); \
    MMA_OP(c1##na##_0, c1##na##_1, c1##na##_2, c1##na##_3, \
           ah1_0, ah1_1, ah1_2, ah1_3, bA0, bA1); \
    MMA_OP(c1##nb##_0, c1##nb##_1, c1##nb##_2, c1##nb##_3, \
           ah1_0, ah1_1, ah1_2, ah1_3, bB0, bB1); \
    MMA_OP(c0##na##_0, c0##na##_1, c0##na##_2, c0##na##_3, \
           al0_0, al0_1, al0_2, al0_3, bA0, bA1); \
    MMA_OP(c0##nb##_0, c0##nb##_1, c0##nb##_2, c0##nb##_3, \
           al0_0, al0_1, al0_2, al0_3, bB0, bB1); \
    MMA_OP(c1##na##_0, c1##na##_1, c1##na##_2, c1##na##_3, \
           al1_0, al1_1, al1_2, al1_3, bA0, bA1); \
    MMA_OP(c1##nb##_0, c1##nb##_1, c1##nb##_2, c1##nb##_3, \
           al1_0, al1_1, al1_2, al1_3, bB0, bB1); \
    MMA_OP(c0##na##_0, c0##na##_1, c0##na##_2, c0##na##_3, \
           ah0_0, ah0_1, ah0_2, ah0_3, lA0, lA1); \
    MMA_OP(c0##nb##_0, c0##nb##_1, c0##nb##_2, c0##nb##_3, \
           ah0_0, ah0_1, ah0_2, ah0_3, lB0, lB1); \
    MMA_OP(c1##na##_0, c1##na##_1, c1##na##_2, c1##na##_3, \
           ah1_0, ah1_1, ah1_2, ah1_3, lA0, lA1); \
    MMA_OP(c1##nb##_0, c1##nb##_1, c1##nb##_2, c1##nb##_3, \
           ah1_0, ah1_1, ah1_2, ah1_3, lB0, lB1); \
} while (0)

#define Q_K16(KX) do { \
    LDSM_OP(ah0_0, ah0_1, ah0_2, ah0_3, Ah + (ao0 ^ (KX))); \
    LDSM_OP(al0_0, al0_1, al0_2, al0_3, Al + (ao0 ^ (KX))); \
    LDSM_OP(ah1_0, ah1_1, ah1_2, ah1_3, Ah + (ao1 ^ (KX))); \
    LDSM_OP(al1_0, al1_1, al1_2, al1_3, Al + (ao1 ^ (KX))); \
    Q_NFP(0, 1, KX); Q_NFP(2, 3, KX); \
    Q_NFP(4, 5, KX); Q_NFP(6, 7, KX); \
} while (0)

#define STORE_Q(m, n) do { \
    int rr = wm * 32 + m * 16 + (lane >> 2); \
    int cc = wn * 64 + n * 8 + (lane & 3) * 2; \
    *(float2*)(Cp + (size_t)rr * ldc + cc) = make_float2(c##m##n##_0, c##m##n##_1); \
    *(float2*)(Cp + (size_t)(rr + 8) * ldc + cc) = make_float2(c##m##n##_2, c##m##n##_3); \
} while (0)

__global__ __launch_bounds__(512, 1)
void qkv3_kernel()
{
    extern __shared__ char smem[];
    uint32_t sbase = smem_to_u32(smem);

    const int mt = blockIdx.x, nt = blockIdx.y;
    const int m0 = mt * 128, n0 = nt * 256;
    const __nv_bfloat16* Ahi = g_Xhi + (size_t)m0 * DIM;
    const __nv_bfloat16* Alo = g_Xlo + (size_t)m0 * DIM;
    const __nv_bfloat16* Bhi = g_Wqkvt_hi + (size_t)n0 * DIM;
    const __nv_bfloat16* Blo = g_Wqkvt_lo + (size_t)n0 * DIM;
    float* Cp; int ldc;
    if (nt < 16)      { Cp = g_Q + (size_t)m0 * 4096 + n0;          ldc = 4096; }
    else if (nt < 20) { Cp = g_K + (size_t)m0 * 1024 + (n0 - 4096); ldc = 1024; }
    else              { Cp = g_V + (size_t)m0 * 1024 + (n0 - 5120); ldc = 1024; }

    const int tid  = threadIdx.x;
    const int lane = tid & 31;
    const int wid  = tid >> 5;     // 0..15
    const int wm   = wid >> 2;     // 0..3 : 32-row slab
    const int wn   = wid & 3;      // 0..3 : 64-col slab

    DECL_ACC(0,0); DECL_ACC(0,1); DECL_ACC(0,2); DECL_ACC(0,3);
    DECL_ACC(0,4); DECL_ACC(0,5); DECL_ACC(0,6); DECL_ACC(0,7);
    DECL_ACC(1,0); DECL_ACC(1,1); DECL_ACC(1,2); DECL_ACC(1,3);
    DECL_ACC(1,4); DECL_ACC(1,5); DECL_ACC(1,6); DECL_ACC(1,7);

    const int NT = DIM / 32;   // 128 iterations

    q_load_stage(sbase, 0, 0,  Ahi, Alo, Bhi, Blo, tid); CP_COMMIT();
    q_load_stage(sbase, 1, 32, Ahi, Alo, Bhi, Blo, tid); CP_COMMIT();

    // A offsets (kh16=0); kh16=1 is ^32 (flips swizzled ch bit1)
    const int arow0 = wm * 32 + ((lane >> 3) & 1) * 8 + (lane & 7);
    const uint32_t ao0 = qsw(arow0,      (lane >> 4));
    const uint32_t ao1 = qsw(arow0 + 16, (lane >> 4));
    // B offsets (kh16=0), x2 loads: lanes 0-15 address two n8 x k8 matrices
    const int brow = wn * 64 + (lane & 7);
    const int bch  = (lane >> 3) & 1;
    const uint32_t bo0 = qsw(brow,      bch);
    const uint32_t bo1 = qsw(brow + 8,  bch);
    const uint32_t bo2 = qsw(brow + 16, bch);
    const uint32_t bo3 = qsw(brow + 24, bch);
    const uint32_t bo4 = qsw(brow + 32, bch);
    const uint32_t bo5 = qsw(brow + 40, bch);
    const uint32_t bo6 = qsw(brow + 48, bch);
    const uint32_t bo7 = qsw(brow + 56, bch);

    for (int i = 0; i < NT; i++) {
        CP_WAIT(1);               // stage i resident
        __syncthreads();          // visibility + all reads of stage i-1 done
        int pf = i + 2;           // prefetch into buffer last read at i-1
        if (pf < NT)
            q_load_stage(sbase, pf % 3, pf * 32, Ahi, Alo, Bhi, Blo, tid);
        CP_COMMIT();

        uint32_t stb = sbase + (uint32_t)(i % 3) * QSTG;
        uint32_t Ah = stb, Al = stb + QBUF_A;
        uint32_t Bh = stb + 2 * QBUF_A, Bl = stb + 2 * QBUF_A + QBUF_B;

        uint32_t ah0_0, ah0_1, ah0_2, ah0_3, ah1_0, ah1_1, ah1_2, ah1_3;
        uint32_t al0_0, al0_1, al0_2, al0_3, al1_0, al1_1, al1_2, al1_3;

        Q_K16(0);    // k16 = 0
        Q_K16(32);   // k16 = 1
    }

    STORE_Q(0,0); STORE_Q(0,1); STORE_Q(0,2); STORE_Q(0,3);
    STORE_Q(0,4); STORE_Q(0,5); STORE_Q(0,6); STORE_Q(0,7);
    STORE_Q(1,0); STORE_Q(1,1); STORE_Q(1,2); STORE_Q(1,3);
    STORE_Q(1,4); STORE_Q(1,5); STORE_Q(1,6); STORE_Q(1,7);
}

// ===========================================================================
// Shared tiling for the out-projection (unchanged R13): CTA 128x128, BK=64,
// 512 threads / 16 warps, warp 32x32. smem row = 64 elems = 8 chunks.
// ===========================================================================
constexpr int GBUF_B    = 16384;               // 128 rows x 128B

__device__ __forceinline__ uint32_t gsw(int row, int ch) {
    return (uint32_t)(row * 128 + ((ch ^ (row & 7)) << 4));
}
__device__ __forceinline__ void load_buf(uint32_t dbase, const void* gp,
                                         int k0, int tid) {
    const __nv_bfloat16* g = (const __nv_bfloat16*)gp;
#pragma unroll
    for (int j = 0; j < 2; j++) {
        int c = tid * 2 + j;            // 0..1023
        int row = c >> 3, ch = c & 7;
        cp16(dbase + gsw(row, ch), g + (size_t)row * DIM + k0 + ch * 8);
    }
}

#define STORE_C(m, n) do { \
    int rr = wm * 32 + m * 16 + (lane >> 2); \
    int cc = wn * 32 + n * 8 + (lane & 3) * 2; \
    *(float2*)(Cp + (size_t)rr * ldc + cc) = make_float2(c##m##n##_0, c##m##n##_1); \
    *(float2*)(Cp + (size_t)(rr + 8) * ldc + cc) = make_float2(c##m##n##_2, c##m##n##_3); \
} while (0)

// ===========================================================================
// 1-term fp16 GEMM (output projection): C = Ch_hi @ Wot_h^T.
// 2 buffers/stage (A,B), 3 stages = 96KB. Single barrier/iter.
// ===========================================================================
constexpr int G2STG_B    = 2 * GBUF_B;          // 32KB
constexpr int GEMM2_SMEM = 3 * G2STG_B;         // 96KB

__device__ __forceinline__ void g_load_stage2(
    uint32_t sbase, int s, int k0,
    const __half* Ahi, const __half* Bhi, int tid)
{
    uint32_t stbase = sbase + (uint32_t)s * G2STG_B;
    load_buf(stbase,          Ahi, k0, tid);
    load_buf(stbase + GBUF_B, Bhi, k0, tid);
}

#define HT1(m, n, i0, i1) \
    MMAH_OP(c##m##n##_0, c##m##n##_1, c##m##n##_2, c##m##n##_3, \
            ah##m##_0, ah##m##_1, ah##m##_2, ah##m##_3, bh##n##_##i0, bh##n##_##i1)

#define GEMM2_K16(AOFF0, AOFF1, i0, i1) \
    LDSM_OP(ah0_0, ah0_1, ah0_2, ah0_3, Ah + (AOFF0)); \
    LDSM_OP(ah1_0, ah1_1, ah1_2, ah1_3, Ah + (AOFF1)); \
    HT1(0,0,i0,i1); HT1(0,1,i0,i1); HT1(0,2,i0,i1); HT1(0,3,i0,i1); \
    HT1(1,0,i0,i1); HT1(1,1,i0,i1); HT1(1,2,i0,i1); HT1(1,3,i0,i1)

#define LOAD_B2_KH2(kh2sel) \
    LDSM_OP(bh0_0, bh0_1, bh0_2, bh0_3, Bh + bo0_##kh2sel); \
    LDSM_OP(bh1_0, bh1_1, bh1_2, bh1_3, Bh + bo1_##kh2sel); \
    LDSM_OP(bh2_0, bh2_1, bh2_2, bh2_3, Bh + bo2_##kh2sel); \
    LDSM_OP(bh3_0, bh3_1, bh3_2, bh3_3, Bh + bo3_##kh2sel)

__global__ __launch_bounds__(512, 1)
void out2_kernel(float* __restrict__ out)
{
    extern __shared__ char smem[];
    uint32_t sbase = smem_to_u32(smem);

    const int m0 = (int)blockIdx.x * 128, n0 = (int)blockIdx.y * 128;
    const __half* Ahi = g_Ch_hi + (size_t)m0 * DIM;
    const __half* Bhi = g_Wot_h + (size_t)n0 * DIM;
    float* Cp = out + (size_t)m0 * DIM + n0;
    const int ldc = DIM;

    const int tid  = threadIdx.x;
    const int lane = tid & 31;
    const int wid  = tid >> 5;
    const int wm   = wid >> 2;
    const int wn   = wid & 3;

    DECL_ACC(0,0); DECL_ACC(0,1); DECL_ACC(0,2); DECL_ACC(0,3);
    DECL_ACC(1,0); DECL_ACC(1,1); DECL_ACC(1,2); DECL_ACC(1,3);

    const int NT = DIM / 64;

    g_load_stage2(sbase, 0, 0,  Ahi, Bhi, tid); CP_COMMIT();
    g_load_stage2(sbase, 1, 64, Ahi, Bhi, tid); CP_COMMIT();

    const int ar0 = wm * 32 + ((lane >> 3) & 1) * 8 + (lane & 7);
    const int ar1 = ar0 + 16;
    const int ln16 = lane >> 4;
    const uint32_t ao0_0 = gsw(ar0, 0 + ln16), ao0_1 = gsw(ar0, 2 + ln16);
    const uint32_t ao0_2 = gsw(ar0, 4 + ln16), ao0_3 = gsw(ar0, 6 + ln16);
    const uint32_t ao1_0 = gsw(ar1, 0 + ln16), ao1_1 = gsw(ar1, 2 + ln16);
    const uint32_t ao1_2 = gsw(ar1, 4 + ln16), ao1_3 = gsw(ar1, 6 + ln16);
    const int ln8 = lane >> 3;
    const uint32_t bo0_0 = gsw(wn*32 + 0  + (lane&7), ln8);
    const uint32_t bo1_0 = gsw(wn*32 + 8  + (lane&7), ln8);
    const uint32_t bo2_0 = gsw(wn*32 + 16 + (lane&7), ln8);
    const uint32_t bo3_0 = gsw(wn*32 + 24 + (lane&7), ln8);
    const uint32_t bo0_1 = gsw(wn*32 + 0  + (lane&7), 4 + ln8);
    const uint32_t bo1_1 = gsw(wn*32 + 8  + (lane&7), 4 + ln8);
    const uint32_t bo2_1 = gsw(wn*32 + 16 + (lane&7), 4 + ln8);
    const uint32_t bo3_1 = gsw(wn*32 + 24 + (lane&7), 4 + ln8);

    for (int i = 0; i < NT; i++) {
        CP_WAIT(1);
        __syncthreads();
        int pf = i + 2;
        if (pf < NT)
            g_load_stage2(sbase, pf % 3, pf * 64, Ahi, Bhi, tid);
        CP_COMMIT();

        uint32_t stb = sbase + (uint32_t)(i % 3) * G2STG_B;
        uint32_t Ah = stb, Bh = stb + GBUF_B;

        DECL_F(bh, 0); DECL_F(bh, 1); DECL_F(bh, 2); DECL_F(bh, 3);
        uint32_t ah0_0, ah0_1, ah0_2, ah0_3, ah1_0, ah1_1, ah1_2, ah1_3;

        LOAD_B2_KH2(0);
        GEMM2_K16(ao0_0, ao1_0, 0, 1);
        GEMM2_K16(ao0_1, ao1_1, 2, 3);
        LOAD_B2_KH2(1);
        GEMM2_K16(ao0_2, ao1_2, 0, 1);
        GEMM2_K16(ao0_3, ao1_3, 2, 3);
    }

    STORE_C(0,0); STORE_C(0,1); STORE_C(0,2); STORE_C(0,3);
    STORE_C(1,0); STORE_C(1,1); STORE_C(1,2); STORE_C(1,3);
}

// ===========================================================================
// Fast exp on the FMA pipe
// ===========================================================================
__device__ __forceinline__ float fexp(float x) {
    float y = x * 1.4426950408889634f;
    y = fmaxf(y, -125.0f);
    float fl = floorf(y);
    float t = y - fl;
    float r = 1.5403530e-4f;
    r = fmaf(r, t, 1.3333558e-3f);
    r = fmaf(r, t, 9.6181291e-3f);
    r = fmaf(r, t, 5.5504109e-2f);
    r = fmaf(r, t, 2.4022651e-1f);
    r = fmaf(r, t, 6.9314718e-1f);
    r = fmaf(r, t, 1.0f);
    float s = __int_as_float(((int)fl + 127) << 23);
    return r * s;
}

// ===========================================================================
// RoPE + scale + split: fp32 Q/K/V -> split bf16 (Q scaled by 1/sqrt(HD))
// ===========================================================================
__global__ void ropesplit_kernel(const int* __restrict__ pos)
{
    int idx = blockIdx.x * blockDim.x + threadIdx.x;
    const int NQP = SEQ * NH * 64;
    const int NKP = SEQ * NKV * 64;
    const int NVP = SEQ * NKV * 64;
    if (idx >= NQP + NKP + NVP) return;

    if (idx < NQP) {
        int i = idx & 63, h = (idx >> 6) & 31, s = idx >> 11;
        size_t o = (size_t)s * (NH * HDIM) + h * HDIM + i;
        float x1 = g_Q[o], x2 = g_Q[o + 64];
        float p = (float)pos[s];
        float freq = (float)exp2(-(double)i * 0.31143075889569021);
        float sn, cs; sincosf(p * freq, &sn, &cs);
        const float sc = 0.08838834764831845f;
        float y1 = (x1 * cs - x2 * sn) * sc;
        float y2 = (x1 * sn + x2 * cs) * sc;
        __nv_bfloat16 hh, ll;
        split1(y1, hh, ll); g_Qhi[o] = hh;      g_Qlo[o] = ll;
        split1(y2, hh, ll); g_Qhi[o + 64] = hh; g_Qlo[o + 64] = ll;
    } else if (idx < NQP + NKP) {
        int t = idx - NQP;
        int i = t & 63, g = (t >> 6) & 7, s = t >> 9;
        size_t o = (size_t)s * (NKV * HDIM) + g * HDIM + i;
        float x1 = g_K[o], x2 = g_K[o + 64];
        float p = (float)pos[s];
        float freq = (float)exp2(-(double)i * 0.31143075889569021);
        float sn, cs; sincosf(p * freq, &sn, &cs);
        float y1 = x1 * cs - x2 * sn;
        float y2 = x1 * sn + x2 * cs;
        __nv_bfloat16 hh, ll;
        split1(y1, hh, ll); g_Khi[o] = hh;      g_Klo[o] = ll;
        split1(y2, hh, ll); g_Khi[o + 64] = hh; g_Klo[o + 64] = ll;
    } else {
        int t = idx - NQP - NKP;
        int i = t & 63, g = (t >> 6) & 7, s = t >> 9;
        size_t o = (size_t)s * (NKV * HDIM) + g * HDIM + i;
        __nv_bfloat16 hh, ll;
        split1(g_V[o], hh, ll);      g_Vhi[o] = hh;      g_Vlo[o] = ll;
        split1(g_V[o + 64], hh, ll); g_Vhi[o + 64] = hh; g_Vlo[o + 64] = ll;
    }
}

// ===========================================================================
// HMMA flash attention (R13-proven; single barrier per kt; fp16 context out)
// ===========================================================================
constexpr int AQ_B     = 32768;
constexpr int AKV_B    = 16384;
constexpr int AST_B    = 4 * AKV_B;
constexpr int AMSK_OFF = 2 * AQ_B + 2 * AST_B;
constexpr int ATTN_SMEM = AMSK_OFF + 768;      // 2 x 64-float mask slots

__device__ __forceinline__ uint32_t asw(int row, int ch) {
    return (uint32_t)(row * 256 + ((ch ^ (row & 7)) << 4));
}
__device__ __forceinline__ uint32_t a_addr(uint32_t base, int m0, int cb, int lane) {
    int row = m0 + ((lane >> 3) & 1) * 8 + (lane & 7);
    return base + asw(row, cb + (lane >> 4));
}
__device__ __forceinline__ uint32_t b_addr(uint32_t base, int n0, int cb, int lane) {
    int row = n0 + (lane & 7);
    return base + asw(row, cb + (lane >> 3));
}
__device__ __forceinline__ uint32_t v_addr(uint32_t base, int t, int nfp, int lane) {
    int g = lane >> 3;
    int row = t * 16 + (g & 1) * 8 + (lane & 7);
    return base + asw(row, nfp * 2 + (g >> 1));
}

__device__ __forceinline__ void load_q_buf(uint32_t dst, const __nv_bfloat16* g,
                                           int q0, int h, int tid) {
#pragma unroll
    for (int j = 0; j < 8; j++) {
        int c = tid * 8 + j;
        int row = c >> 4, ch = c & 15;
        cp16(dst + asw(row, ch),
             g + (size_t)(q0 + row) * (NH * HDIM) + h * HDIM + ch * 8);
    }
}
__device__ __forceinline__ void load_kv_arr(uint32_t dst, const __nv_bfloat16* g,
                                            int s0, int gkv, int tid) {
#pragma unroll
    for (int j = 0; j < 4; j++) {
        int c = tid * 4 + j;
        int row = c >> 4, ch = c & 15;
        cp16(dst + asw(row, ch),
             g + (size_t)(s0 + row) * (NKV * HDIM) + gkv * HDIM + ch * 8);
    }
}

#define DECL_S(n) float s##n##_0, s##n##_1, s##n##_2, s##n##_3
#define ZERO_S(n) s##n##_0 = 0.f; s##n##_1 = 0.f; s##n##_2 = 0.f; s##n##_3 = 0.f
#define DECL_O(n) float o##n##_0 = 0.f, o##n##_1 = 0.f, o##n##_2 = 0.f, o##n##_3 = 0.f

#define SMMA_T(nf, A0,A1,A2,A3, B0,B1) \
    MMA_OP(s##nf##_0, s##nf##_1, s##nf##_2, s##nf##_3, A0,A1,A2,A3, B0,B1)

#define S_NF2(na, nb) do { \
    uint32_t kA0,kA1,kA2,kA3, lA0,lA1,lA2,lA3; \
    uint32_t kB0,kB1,kB2,kB3, lB0,lB1,lB2,lB3; \
    LDSM_OP(kA0,kA1,kA2,kA3, b_addr(KhB, (na)*8, ks2*4, lane)); \
    LDSM_OP(kB0,kB1,kB2,kB3, b_addr(KhB, (nb)*8, ks2*4, lane)); \
    LDSM_OP(lA0,lA1,lA2,lA3, b_addr(KlB, (na)*8, ks2*4, lane)); \
    LDSM_OP(lB0,lB1,lB2,lB3, b_addr(KlB, (nb)*8, ks2*4, lane)); \
    SMMA_T(na, qh0,qh1,qh2,qh3, kA0,kA1); \
    SMMA_T(nb, qh0,qh1,qh2,qh3, kB0,kB1); \
    SMMA_T(na, ql0,ql1,ql2,ql3, kA0,kA1); \
    SMMA_T(nb, ql0,ql1,ql2,ql3, kB0,kB1); \
    SMMA_T(na, qh0,qh1,qh2,qh3, lA0,lA1); \
    SMMA_T(nb, qh0,qh1,qh2,qh3, lB0,lB1); \
    SMMA_T(na, qh4,qh5,qh6,qh7, kA2,kA3); \
    SMMA_T(nb, qh4,qh5,qh6,qh7, kB2,kB3); \
    SMMA_T(na, ql4,ql5,ql6,ql7, kA2,kA3); \
    SMMA_T(nb, ql4,ql5,ql6,ql7, kB2,kB3); \
    SMMA_T(na, qh4,qh5,qh6,qh7, lA2,lA3); \
    SMMA_T(nb, qh4,qh5,qh6,qh7, lB2,lB3); \
} while (0)

#define MASK_NF(nf) do { \
    int lc = (nf) * 8 + ((lane & 3) << 1); \
    float mA = mskp[lc], mB = mskp[lc + 1]; \
    int cg = k0 + lc; \
    s##nf##_0 += (mA > 0.f && (!cz || cg     <= rg0)) ? 0.f : -1e30f; \
    s##nf##_1 += (mB > 0.f && (!cz || cg + 1 <= rg0)) ? 0.f : -1e30f; \
    s##nf##_2 += (mA > 0.f && (!cz || cg     <= rg1)) ? 0.f : -1e30f; \
    s##nf##_3 += (mB > 0.f && (!cz || cg + 1 <= rg1)) ? 0.f : -1e30f; \
} while (0)

#define MAX_NF(nf) \
    mx0 = fmaxf(mx0, fmaxf(s##nf##_0, s##nf##_1)); \
    mx1 = fmaxf(mx1, fmaxf(s##nf##_2, s##nf##_3))

#define EXP_NF(nf) \
    s##nf##_0 = fexp(s##nf##_0 - mn0); sum0 += s##nf##_0; \
    s##nf##_1 = fexp(s##nf##_1 - mn0); sum0 += s##nf##_1; \
    s##nf##_2 = fexp(s##nf##_2 - mn1); sum1 += s##nf##_2; \
    s##nf##_3 = fexp(s##nf##_3 - mn1); sum1 += s##nf##_3

#define SCALE_O(n) \
    o##n##_0 *= al0; o##n##_1 *= al0; o##n##_2 *= al1; o##n##_3 *= al1

#define OMMA_T(on, A0,A1,A2,A3, B0,B1) \
    MMA_OP(o##on##_0, o##on##_1, o##on##_2, o##on##_3, A0,A1,A2,A3, B0,B1)

#define PV_NFP(tt, nfp, oA, oB) do { \
    uint32_t vh0,vh1,vh2,vh3, vl0,vl1,vl2,vl3; \
    LDSMT_OP(vh0,vh1,vh2,vh3, v_addr(VhB, tt, nfp, lane)); \
    LDSMT_OP(vl0,vl1,vl2,vl3, v_addr(VlB, tt, nfp, lane)); \
    OMMA_T(oA, pa0,pa1,pa2,pa3, vh0,vh1); \
    OMMA_T(oB, pa0,pa1,pa2,pa3, vh2,vh3); \
    OMMA_T(oA, la0,la1,la2,la3, vh0,vh1); \
    OMMA_T(oB, la0,la1,la2,la3, vh2,vh3); \
    OMMA_T(oA, pa0,pa1,pa2,pa3, vl0,vl1); \
    OMMA_T(oB, pa0,pa1,pa2,pa3, vl2,vl3); \
} while (0)

#define PVT(e, f, tt) do { \
    uint32_t pa0,pa1,pa2,pa3, la0,la1,la2,la3; \
    packsplit(s##e##_0, s##e##_1, pa0, la0); \
    packsplit(s##e##_2, s##e##_3, pa1, la1); \
    packsplit(s##f##_0, s##f##_1, pa2, la2); \
    packsplit(s##f##_2, s##f##_3, pa3, la3); \
    PV_NFP(tt, 0, 0, 1);  PV_NFP(tt, 1, 2, 3); \
    PV_NFP(tt, 2, 4, 5);  PV_NFP(tt, 3, 6, 7); \
    PV_NFP(tt, 4, 8, 9);  PV_NFP(tt, 5, 10, 11); \
    PV_NFP(tt, 6, 12, 13); PV_NFP(tt, 7, 14, 15); \
} while (0)

#define EPI_O(n) do { \
    __half2 hv = __floats2half2_rn(o##n##_0 * il0, o##n##_1 * il0); \
    *(__half2*)(g_Ch_hi + ro0 + (n) * 8) = hv; \
    hv = __floats2half2_rn(o##n##_2 * il1, o##n##_3 * il1); \
    *(__half2*)(g_Ch_hi + ro1 + (n) * 8) = hv; \
} while (0)

__global__ __launch_bounds__(256, 1)
void attn_mma_kernel(const float* __restrict__ amask)
{
    extern __shared__ char smem[];
    uint32_t sbase = smem_to_u32(smem);
    float* msk = (float*)(smem + AMSK_OFF);   // 2 slots x 64

    const int h    = blockIdx.x;
    const int qt   = (int)gridDim.y - 1 - (int)blockIdx.y;
    const int gkv  = h >> 2;
    const int tid  = threadIdx.x;
    const int lane = tid & 31;
    const int wid  = tid >> 5;
    const int q0   = qt * 128;

    const uint32_t QhB = sbase, QlB = sbase + AQ_B;

    load_q_buf(QhB, g_Qhi, q0, h, tid);
    load_q_buf(QlB, g_Qlo, q0, h, tid);
    {
        uint32_t st = sbase + 2 * AQ_B;
        load_kv_arr(st,             g_Khi, 0, gkv, tid);
        load_kv_arr(st + AKV_B,     g_Klo, 0, gkv, tid);
        load_kv_arr(st + 2 * AKV_B, g_Vhi, 0, gkv, tid);
        load_kv_arr(st + 3 * AKV_B, g_Vlo, 0, gkv, tid);
    }
    CP_COMMIT();

    DECL_O(0);  DECL_O(1);  DECL_O(2);  DECL_O(3);
    DECL_O(4);  DECL_O(5);  DECL_O(6);  DECL_O(7);
    DECL_O(8);  DECL_O(9);  DECL_O(10); DECL_O(11);
    DECL_O(12); DECL_O(13); DECL_O(14); DECL_O(15);
    float m0 = -1e30f, m1 = -1e30f, l0 = 0.f, l1 = 0.f;

    const int rg0 = q0 + wid * 16 + (lane >> 2);
    const int rg1 = rg0 + 8;
    const int ktmax = 2 * qt + 1;

    for (int kt = 0; kt <= ktmax; kt++) {
        const int k0 = kt * 64;
        const uint32_t stg = sbase + 2 * AQ_B + (uint32_t)(kt & 1) * AST_B;
        float* mskp = msk + (kt & 1) * 64;

        if (tid < 64) mskp[tid] = amask[k0 + tid];
        CP_WAIT(0);               // stage kt (and Q on kt==0) resident
        __syncthreads();          // visibility + all reads of stage kt-1 done

        if (kt < ktmax) {
            uint32_t nst = sbase + 2 * AQ_B + (uint32_t)((kt + 1) & 1) * AST_B;
            int ns = (kt + 1) * 64;
            load_kv_arr(nst,             g_Khi, ns, gkv, tid);
            load_kv_arr(nst + AKV_B,     g_Klo, ns, gkv, tid);
            load_kv_arr(nst + 2 * AKV_B, g_Vhi, ns, gkv, tid);
            load_kv_arr(nst + 3 * AKV_B, g_Vlo, ns, gkv, tid);
            CP_COMMIT();
        }

        const uint32_t KhB = stg, KlB = stg + AKV_B;
        const uint32_t VhB = stg + 2 * AKV_B, VlB = stg + 3 * AKV_B;
        const bool cz = (kt >= 2 * qt);

        DECL_S(0); DECL_S(1); DECL_S(2); DECL_S(3);
        DECL_S(4); DECL_S(5); DECL_S(6); DECL_S(7);
        ZERO_S(0); ZERO_S(1); ZERO_S(2); ZERO_S(3);
        ZERO_S(4); ZERO_S(5); ZERO_S(6); ZERO_S(7);

#pragma unroll
        for (int ks2 = 0; ks2 < 4; ks2++) {
            uint32_t qh0, qh1, qh2, qh3, qh4, qh5, qh6, qh7;
            uint32_t ql0, ql1, ql2, ql3, ql4, ql5, ql6, ql7;
            LDSM_OP(qh0, qh1, qh2, qh3, a_addr(QhB, wid * 16, ks2 * 4, lane));
            LDSM_OP(qh4, qh5, qh6, qh7, a_addr(QhB, wid * 16, ks2 * 4 + 2, lane));
            LDSM_OP(ql0, ql1, ql2, ql3, a_addr(QlB, wid * 16, ks2 * 4, lane));
            LDSM_OP(ql4, ql5, ql6, ql7, a_addr(QlB, wid * 16, ks2 * 4 + 2, lane));
            S_NF2(0, 1); S_NF2(2, 3); S_NF2(4, 5); S_NF2(6, 7);
        }

        MASK_NF(0); MASK_NF(1); MASK_NF(2); MASK_NF(3);
        MASK_NF(4); MASK_NF(5); MASK_NF(6); MASK_NF(7);

        float mx0 = -1e30f, mx1 = -1e30f;
        MAX_NF(0); MAX_NF(1); MAX_NF(2); MAX_NF(3);
        MAX_NF(4); MAX_NF(5); MAX_NF(6); MAX_NF(7);
        mx0 = fmaxf(mx0, __shfl_xor_sync(0xffffffffu, mx0, 1, 4));
        mx0 = fmaxf(mx0, __shfl_xor_sync(0xffffffffu, mx0, 2, 4));
        mx1 = fmaxf(mx1, __shfl_xor_sync(0xffffffffu, mx1, 1, 4));
        mx1 = fmaxf(mx1, __shfl_xor_sync(0xffffffffu, mx1, 2, 4));

        float mn0 = fmaxf(m0, mx0), mn1 = fmaxf(m1, mx1);
        float al0 = fexp(m0 - mn0), al1 = fexp(m1 - mn1);
        m0 = mn0; m1 = mn1;

        float sum0 = 0.f, sum1 = 0.f;
        EXP_NF(0); EXP_NF(1); EXP_NF(2); EXP_NF(3);
        EXP_NF(4); EXP_NF(5); EXP_NF(6); EXP_NF(7);
        sum0 += __shfl_xor_sync(0xffffffffu, sum0, 1, 4);
        sum0 += __shfl_xor_sync(0xffffffffu, sum0, 2, 4);
        sum1 += __shfl_xor_sync(0xffffffffu, sum1, 1, 4);
        sum1 += __shfl_xor_sync(0xffffffffu, sum1, 2, 4);
        l0 = l0 * al0 + sum0;
        l1 = l1 * al1 + sum1;

        SCALE_O(0);  SCALE_O(1);  SCALE_O(2);  SCALE_O(3);
        SCALE_O(4);  SCALE_O(5);  SCALE_O(6);  SCALE_O(7);
        SCALE_O(8);  SCALE_O(9);  SCALE_O(10); SCALE_O(11);
        SCALE_O(12); SCALE_O(13); SCALE_O(14); SCALE_O(15);

        PVT(0, 1, 0); PVT(2, 3, 1); PVT(4, 5, 2); PVT(6, 7, 3);
    }

    const float il0 = 1.0f / l0, il1 = 1.0f / l1;
    const size_t ro0 = (size_t)rg0 * DIM + h * HDIM + ((lane & 3) << 1);
    const size_t ro1 = ro0 + (size_t)8 * DIM;
    EPI_O(0);  EPI_O(1);  EPI_O(2);  EPI_O(3);
    EPI_O(4);  EPI_O(5);  EPI_O(6);  EPI_O(7);
    EPI_O(8);  EPI_O(9);  EPI_O(10); EPI_O(11);
    EPI_O(12); EPI_O(13); EPI_O(14); EPI_O(15);
}

// ===========================================================================
extern "C" void kernel_launch(void* const* d_in, const int* in_sizes, int n_in,
                              void* d_out, int out_size)
{
    const float* X   = (const float*)d_in[0];
    const float* am  = (const float*)d_in[1];
    const int*   pos = (const int*)  d_in[2];
    const float* wq  = (const float*)d_in[3];
    const float* wk  = (const float*)d_in[4];
    const float* wv  = (const float*)d_in[5];
    const float* wo  = (const float*)d_in[6];
    float* out = (float*)d_out;

    (void)in_sizes; (void)n_in; (void)out_size;

    // 1. Split conversions
    xsplit_kernel<<<(SEQ * DIM / 4 + 255) / 256, 256>>>(X, SEQ * DIM / 4);
    wsplit_t_kernel<<<dim3(4096 / 32, 4096 / 32), 256>>>(wq, 4096, 0);
    wsplit_t_kernel<<<dim3(1024 / 32, 4096 / 32), 256>>>(wk, 1024, 4096);
    wsplit_t_kernel<<<dim3(1024 / 32, 4096 / 32), 256>>>(wv, 1024, 5120);
    wsplit_wo_kernel<<<dim3(4096 / 32, 4096 / 32), 256>>>(wo);

    // 2. QKV projection (HMMA split-bf16 3-term, CTA 128x256 warp 32x64)
    cudaFuncSetAttribute((const void*)qkv3_kernel,
                         cudaFuncAttributeMaxDynamicSharedMemorySize, QKV_SMEM);
    qkv3_kernel<<<dim3(16, 24), 512, QKV_SMEM>>>();

    // 3. RoPE + scale + split-bf16 conversion of Q/K/V
    int tot = SEQ * NH * 64 + 2 * SEQ * NKV * 64;
    ropesplit_kernel<<<(tot + 255) / 256, 256>>>(pos);

    // 4. HMMA flash attention (single barrier/kt; fp16 context out)
    cudaFuncSetAttribute((const void*)attn_mma_kernel,
                         cudaFuncAttributeMaxDynamicSharedMemorySize, ATTN_SMEM);
    attn_mma_kernel<<<dim3(NH, SEQ / 128), 256, ATTN_SMEM>>>(am);

    // 5. Output projection (pure fp16 1-term HMMA)
    cudaFuncSetAttribute((const void*)out2_kernel,
                         cudaFuncAttributeMaxDynamicSharedMemorySize, GEMM2_SMEM);
    out2_kernel<<<dim3(16, 32), 512, GEMM2_SMEM>>>(out);
}

// round 17
// speedup vs baseline: 1.0624x; 1.0597x over previous
#include <cuda_runtime.h>
#include <cuda_bf16.h>
#include <cuda_fp16.h>
#include <math.h>
#include <cstdint>
#include <cstring>

// Problem shape constants
constexpr int SEQ  = 2048;
constexpr int DIM  = 4096;
constexpr int NH   = 32;
constexpr int NKV  = 8;
constexpr int HDIM = 128;

// Scratch (device globals: allocation-free rule)
__device__ float g_Q[SEQ * NH * HDIM];     // fp32 QKV-GEMM outputs
__device__ float g_K[SEQ * NKV * HDIM];
__device__ float g_V[SEQ * NKV * HDIM];

// Split-bf16 operands (16B-aligned for cp.async)
__device__ __align__(256) __nv_bfloat16 g_Xhi[SEQ * DIM];
__device__ __align__(256) __nv_bfloat16 g_Xlo[SEQ * DIM];
__device__ __align__(256) __nv_bfloat16 g_Wqkvt_hi[6144 * DIM];
__device__ __align__(256) __nv_bfloat16 g_Wqkvt_lo[6144 * DIM];
// fp16 operands for the 1-term output projection
__device__ __align__(256) __half g_Wot_h[DIM * DIM];   // [N=4096][K=4096] = Wo^T, fp16
__device__ __align__(256) __half g_Ch_hi[SEQ * DIM];   // attention out, fp16
// Split bf16 Q/K for HMMA attention (RoPE + scale folded into Q); V fp16 1-term
__device__ __align__(256) __nv_bfloat16 g_Qhi[SEQ * NH * HDIM];
__device__ __align__(256) __nv_bfloat16 g_Qlo[SEQ * NH * HDIM];
__device__ __align__(256) __nv_bfloat16 g_Khi[SEQ * NKV * HDIM];
__device__ __align__(256) __nv_bfloat16 g_Klo[SEQ * NKV * HDIM];
__device__ __align__(256) __half        g_Vh [SEQ * NKV * HDIM];

// ===========================================================================
// PTX helpers
// ===========================================================================
__device__ __forceinline__ uint32_t smem_to_u32(const void* smem_ptr) {
    uint32_t addr;
    asm("{ .reg .u64 tmp; cvta.to.shared.u64 tmp, %1; cvt.u32.u64 %0, tmp; }"
        : "=r"(addr) : "l"(smem_ptr));
    return addr;
}
__device__ __forceinline__ void cp16(uint32_t dst, const void* src) {
    asm volatile("cp.async.cg.shared.global [%0], [%1], 16;\n" :: "r"(dst), "l"(src));
}
#define CP_COMMIT() asm volatile("cp.async.commit_group;\n" ::: "memory")
#define CP_WAIT(n)  asm volatile("cp.async.wait_group %0;\n" :: "n"(n) : "memory")

#define LDSM_OP(r0, r1, r2, r3, addr) \
    asm volatile("ldmatrix.sync.aligned.m8n8.x4.shared.b16 {%0,%1,%2,%3}, [%4];" \
        : "=r"(r0), "=r"(r1), "=r"(r2), "=r"(r3) : "r"(addr))
#define LDSM2_OP(r0, r1, addr) \
    asm volatile("ldmatrix.sync.aligned.m8n8.x2.shared.b16 {%0,%1}, [%2];" \
        : "=r"(r0), "=r"(r1) : "r"(addr))
#define LDSMT_OP(r0, r1, r2, r3, addr) \
    asm volatile("ldmatrix.sync.aligned.m8n8.x4.trans.shared.b16 {%0,%1,%2,%3}, [%4];" \
        : "=r"(r0), "=r"(r1), "=r"(r2), "=r"(r3) : "r"(addr))

#define MMA_OP(d0, d1, d2, d3, A0, A1, A2, A3, B0, B1) \
    asm volatile("mma.sync.aligned.m16n8k16.row.col.f32.bf16.bf16.f32 " \
        "{%0,%1,%2,%3}, {%4,%5,%6,%7}, {%8,%9}, {%0,%1,%2,%3};" \
        : "+f"(d0), "+f"(d1), "+f"(d2), "+f"(d3) \
        : "r"(A0), "r"(A1), "r"(A2), "r"(A3), "r"(B0), "r"(B1))

#define MMAH_OP(d0, d1, d2, d3, A0, A1, A2, A3, B0, B1) \
    asm volatile("mma.sync.aligned.m16n8k16.row.col.f32.f16.f16.f32 " \
        "{%0,%1,%2,%3}, {%4,%5,%6,%7}, {%8,%9}, {%0,%1,%2,%3};" \
        : "+f"(d0), "+f"(d1), "+f"(d2), "+f"(d3) \
        : "r"(A0), "r"(A1), "r"(A2), "r"(A3), "r"(B0), "r"(B1))

// ===========================================================================
// Split conversions
// ===========================================================================
__device__ __forceinline__ void split1(float x, __nv_bfloat16& h, __nv_bfloat16& l) {
    h = __float2bfloat16(x);
    l = __float2bfloat16(x - __bfloat162float(h));
}
// pack two floats to fp16x2 word (hi = y)
__device__ __forceinline__ uint32_t f2h2(float x, float y) {
    __half2 h = __floats2half2_rn(x, y);
    uint32_t u; memcpy(&u, &h, 4);
    return u;
}

__global__ void xsplit_kernel(const float* __restrict__ X, int total4) {
    int idx = blockIdx.x * blockDim.x + threadIdx.x;
    if (idx >= total4) return;
    float4 v = ((const float4*)X)[idx];
    __nv_bfloat16 h0, h1, h2, h3, l0, l1, l2, l3;
    split1(v.x, h0, l0); split1(v.y, h1, l1);
    split1(v.z, h2, l2); split1(v.w, h3, l3);
    __nv_bfloat162* H2 = (__nv_bfloat162*)(g_Xhi + (size_t)idx * 4);
    __nv_bfloat162* L2 = (__nv_bfloat162*)(g_Xlo + (size_t)idx * 4);
    H2[0] = __nv_bfloat162(h0, h1); H2[1] = __nv_bfloat162(h2, h3);
    L2[0] = __nv_bfloat162(l0, l1); L2[1] = __nv_bfloat162(l2, l3);
}

// QKV weights: transpose + bf16 hi/lo split
__global__ void wsplit_t_kernel(const float* __restrict__ W, int N, int dst_row_off) {
    __shared__ float s[32][33];
    int n0 = blockIdx.x * 32, k0 = blockIdx.y * 32;
    int lx = threadIdx.x & 31, ly = threadIdx.x >> 5;
#pragma unroll
    for (int r = 0; r < 4; r++) {
        int row = ly + r * 8;
        s[row][lx] = W[(size_t)(k0 + row) * N + n0 + lx];
    }
    __syncthreads();
#pragma unroll
    for (int r = 0; r < 4; r++) {
        int nrow = ly + r * 8;
        float x = s[lx][nrow];
        __nv_bfloat16 h, l; split1(x, h, l);
        size_t o = (size_t)(dst_row_off + n0 + nrow) * DIM + k0 + lx;
        g_Wqkvt_hi[o] = h; g_Wqkvt_lo[o] = l;
    }
}

// Wo: transpose + fp16 (1-term out-projection)
__global__ void wsplit_wo_kernel(const float* __restrict__ W) {
    __shared__ float s[32][33];
    int n0 = blockIdx.x * 32, k0 = blockIdx.y * 32;
    int lx = threadIdx.x & 31, ly = threadIdx.x >> 5;
#pragma unroll
    for (int r = 0; r < 4; r++) {
        int row = ly + r * 8;
        s[row][lx] = W[(size_t)(k0 + row) * DIM + n0 + lx];
    }
    __syncthreads();
#pragma unroll
    for (int r = 0; r < 4; r++) {
        int nrow = ly + r * 8;
        g_Wot_h[(size_t)(n0 + nrow) * DIM + k0 + lx] = __float2half_rn(s[lx][nrow]);
    }
}

// ===========================================================================
// QKV GEMM (frozen R16): CTA 128x256, BK=32, 512 threads / 16 warps, warp
// tile 32x64. 3-term split-bf16.
// ===========================================================================
constexpr int QBUF_A   = 8192;
constexpr int QBUF_B   = 16384;
constexpr int QSTG     = 2 * QBUF_A + 2 * QBUF_B;  // 48KB
constexpr int QKV_SMEM = 3 * QSTG;                 // 144KB

__device__ __forceinline__ uint32_t qsw(int row, int ch) {
    return (uint32_t)(row * 64 + ((ch ^ ((row >> 1) & 3)) << 4));
}
__device__ __forceinline__ void q_load_a(uint32_t dbase, const __nv_bfloat16* g,
                                         int k0, int tid) {
    int row = tid >> 2, ch = tid & 3;
    cp16(dbase + qsw(row, ch), g + (size_t)row * DIM + k0 + ch * 8);
}
__device__ __forceinline__ void q_load_b(uint32_t dbase, const __nv_bfloat16* g,
                                         int k0, int tid) {
#pragma unroll
    for (int j = 0; j < 2; j++) {
        int c = tid * 2 + j;
        int row = c >> 2, ch = c & 3;
        cp16(dbase + qsw(row, ch), g + (size_t)row * DIM + k0 + ch * 8);
    }
}
__device__ __forceinline__ void q_load_stage(
    uint32_t sbase, int s, int k0,
    const __nv_bfloat16* Ahi, const __nv_bfloat16* Alo,
    const __nv_bfloat16* Bhi, const __nv_bfloat16* Blo, int tid)
{
    uint32_t st = sbase + (uint32_t)s * QSTG;
    q_load_a(st,                     Ahi, k0, tid);
    q_load_a(st + QBUF_A,            Alo, k0, tid);
    q_load_b(st + 2 * QBUF_A,        Bhi, k0, tid);
    q_load_b(st + 2 * QBUF_A + QBUF_B, Blo, k0, tid);
}

#define DECL_ACC(m, n) \
    float c##m##n##_0 = 0.f, c##m##n##_1 = 0.f, c##m##n##_2 = 0.f, c##m##n##_3 = 0.f
#define DECL_F(p, n) uint32_t p##n##_0, p##n##_1, p##n##_2, p##n##_3

#define Q_NFP(na, nb, KX) do { \
    uint32_t bA0, bA1, bB0, bB1, lA0, lA1, lB0, lB1; \
    LDSM2_OP(bA0, bA1, Bh + (bo##na ^ (KX))); \
    LDSM2_OP(bB0, bB1, Bh + (bo##nb ^ (KX))); \
    LDSM2_OP(lA0, lA1, Bl + (bo##na ^ (KX))); \
    LDSM2_OP(lB0, lB1, Bl + (bo##nb ^ (KX))); \
    MMA_OP(c0##na##_0, c0##na##_1, c0##na##_2, c0##na##_3, \
           ah0_0, ah0_1, ah0_2, ah0_3, bA0, bA1); \
    MMA_OP(c0##nb##_0, c0##nb##_1, c0##nb##_2, c0##nb##_3, \
           ah0_0, ah0_1, ah0_2, ah0_3, bB0, bB1); \
    MMA_OP(c1##na##_0, c1##na##_1, c1##na##_2, c1##na##_3, \
           ah1_0, ah1_1, ah1_2, ah1_3, bA0, bA1); \
    MMA_OP(c1##nb##_0, c1##nb##_1, c1##nb##_2, c1##nb##_3, \
           ah1_0, ah1_1, ah1_2, ah1_3, bB0, bB1); \
    MMA_OP(c0##na##_0, c0##na##_1, c0##na##_2, c0##na##_3, \
           al0_0, al0_1, al0_2, al0_3, bA0, bA1); \
    MMA_OP(c0##nb##_0, c0##nb##_1, c0##nb##_2, c0##nb##_3, \
           al0_0, al0_1, al0_2, al0_3, bB0, bB1); \
    MMA_OP(c1##na##_0, c1##na##_1, c1##na##_2, c1##na##_3, \
           al1_0, al1_1, al1_2, al1_3, bA0, bA1); \
    MMA_OP(c1##nb##_0, c1##nb##_1, c1##nb##_2, c1##nb##_3, \
           al1_0, al1_1, al1_2, al1_3, bB0, bB1); \
    MMA_OP(c0##na##_0, c0##na##_1, c0##na##_2, c0##na##_3, \
           ah0_0, ah0_1, ah0_2, ah0_3, lA0, lA1); \
    MMA_OP(c0##nb##_0, c0##nb##_1, c0##nb##_2, c0##nb##_3, \
           ah0_0, ah0_1, ah0_2, ah0_3, lB0, lB1); \
    MMA_OP(c1##na##_0, c1##na##_1, c1##na##_2, c1##na##_3, \
           ah1_0, ah1_1, ah1_2, ah1_3, lA0, lA1); \
    MMA_OP(c1##nb##_0, c1##nb##_1, c1##nb##_2, c1##nb##_3, \
           ah1_0, ah1_1, ah1_2, ah1_3, lB0, lB1); \
} while (0)

#define Q_K16(KX) do { \
    LDSM_OP(ah0_0, ah0_1, ah0_2, ah0_3, Ah + (ao0 ^ (KX))); \
    LDSM_OP(al0_0, al0_1, al0_2, al0_3, Al + (ao0 ^ (KX))); \
    LDSM_OP(ah1_0, ah1_1, ah1_2, ah1_3, Ah + (ao1 ^ (KX))); \
    LDSM_OP(al1_0, al1_1, al1_2, al1_3, Al + (ao1 ^ (KX))); \
    Q_NFP(0, 1, KX); Q_NFP(2, 3, KX); \
    Q_NFP(4, 5, KX); Q_NFP(6, 7, KX); \
} while (0)

#define STORE_Q(m, n) do { \
    int rr = wm * 32 + m * 16 + (lane >> 2); \
    int cc = wn * 64 + n * 8 + (lane & 3) * 2; \
    *(float2*)(Cp + (size_t)rr * ldc + cc) = make_float2(c##m##n##_0, c##m##n##_1); \
    *(float2*)(Cp + (size_t)(rr + 8) * ldc + cc) = make_float2(c##m##n##_2, c##m##n##_3); \
} while (0)

__global__ __launch_bounds__(512, 1)
void qkv3_kernel()
{
    extern __shared__ char smem[];
    uint32_t sbase = smem_to_u32(smem);

    const int mt = blockIdx.x, nt = blockIdx.y;
    const int m0 = mt * 128, n0 = nt * 256;
    const __nv_bfloat16* Ahi = g_Xhi + (size_t)m0 * DIM;
    const __nv_bfloat16* Alo = g_Xlo + (size_t)m0 * DIM;
    const __nv_bfloat16* Bhi = g_Wqkvt_hi + (size_t)n0 * DIM;
    const __nv_bfloat16* Blo = g_Wqkvt_lo + (size_t)n0 * DIM;
    float* Cp; int ldc;
    if (nt < 16)      { Cp = g_Q + (size_t)m0 * 4096 + n0;          ldc = 4096; }
    else if (nt < 20) { Cp = g_K + (size_t)m0 * 1024 + (n0 - 4096); ldc = 1024; }
    else              { Cp = g_V + (size_t)m0 * 1024 + (n0 - 5120); ldc = 1024; }

    const int tid  = threadIdx.x;
    const int lane = tid & 31;
    const int wid  = tid >> 5;
    const int wm   = wid >> 2;
    const int wn   = wid & 3;

    DECL_ACC(0,0); DECL_ACC(0,1); DECL_ACC(0,2); DECL_ACC(0,3);
    DECL_ACC(0,4); DECL_ACC(0,5); DECL_ACC(0,6); DECL_ACC(0,7);
    DECL_ACC(1,0); DECL_ACC(1,1); DECL_ACC(1,2); DECL_ACC(1,3);
    DECL_ACC(1,4); DECL_ACC(1,5); DECL_ACC(1,6); DECL_ACC(1,7);

    const int NT = DIM / 32;

    q_load_stage(sbase, 0, 0,  Ahi, Alo, Bhi, Blo, tid); CP_COMMIT();
    q_load_stage(sbase, 1, 32, Ahi, Alo, Bhi, Blo, tid); CP_COMMIT();

    const int arow0 = wm * 32 + ((lane >> 3) & 1) * 8 + (lane & 7);
    const uint32_t ao0 = qsw(arow0,      (lane >> 4));
    const uint32_t ao1 = qsw(arow0 + 16, (lane >> 4));
    const int brow = wn * 64 + (lane & 7);
    const int bch  = (lane >> 3) & 1;
    const uint32_t bo0 = qsw(brow,      bch);
    const uint32_t bo1 = qsw(brow + 8,  bch);
    const uint32_t bo2 = qsw(brow + 16, bch);
    const uint32_t bo3 = qsw(brow + 24, bch);
    const uint32_t bo4 = qsw(brow + 32, bch);
    const uint32_t bo5 = qsw(brow + 40, bch);
    const uint32_t bo6 = qsw(brow + 48, bch);
    const uint32_t bo7 = qsw(brow + 56, bch);

    for (int i = 0; i < NT; i++) {
        CP_WAIT(1);
        __syncthreads();
        int pf = i + 2;
        if (pf < NT)
            q_load_stage(sbase, pf % 3, pf * 32, Ahi, Alo, Bhi, Blo, tid);
        CP_COMMIT();

        uint32_t stb = sbase + (uint32_t)(i % 3) * QSTG;
        uint32_t Ah = stb, Al = stb + QBUF_A;
        uint32_t Bh = stb + 2 * QBUF_A, Bl = stb + 2 * QBUF_A + QBUF_B;

        uint32_t ah0_0, ah0_1, ah0_2, ah0_3, ah1_0, ah1_1, ah1_2, ah1_3;
        uint32_t al0_0, al0_1, al0_2, al0_3, al1_0, al1_1, al1_2, al1_3;

        Q_K16(0);
        Q_K16(32);
    }

    STORE_Q(0,0); STORE_Q(0,1); STORE_Q(0,2); STORE_Q(0,3);
    STORE_Q(0,4); STORE_Q(0,5); STORE_Q(0,6); STORE_Q(0,7);
    STORE_Q(1,0); STORE_Q(1,1); STORE_Q(1,2); STORE_Q(1,3);
    STORE_Q(1,4); STORE_Q(1,5); STORE_Q(1,6); STORE_Q(1,7);
}

// ===========================================================================
// Out-projection tiling (frozen R13): CTA 128x128, BK=64, 512 threads.
// ===========================================================================
constexpr int GBUF_B    = 16384;

__device__ __forceinline__ uint32_t gsw(int row, int ch) {
    return (uint32_t)(row * 128 + ((ch ^ (row & 7)) << 4));
}
__device__ __forceinline__ void load_buf(uint32_t dbase, const void* gp,
                                         int k0, int tid) {
    const __nv_bfloat16* g = (const __nv_bfloat16*)gp;
#pragma unroll
    for (int j = 0; j < 2; j++) {
        int c = tid * 2 + j;
        int row = c >> 3, ch = c & 7;
        cp16(dbase + gsw(row, ch), g + (size_t)row * DIM + k0 + ch * 8);
    }
}

#define STORE_C(m, n) do { \
    int rr = wm * 32 + m * 16 + (lane >> 2); \
    int cc = wn * 32 + n * 8 + (lane & 3) * 2; \
    *(float2*)(Cp + (size_t)rr * ldc + cc) = make_float2(c##m##n##_0, c##m##n##_1); \
    *(float2*)(Cp + (size_t)(rr + 8) * ldc + cc) = make_float2(c##m##n##_2, c##m##n##_3); \
} while (0)

constexpr int G2STG_B    = 2 * GBUF_B;
constexpr int GEMM2_SMEM = 3 * G2STG_B;

__device__ __forceinline__ void g_load_stage2(
    uint32_t sbase, int s, int k0,
    const __half* Ahi, const __half* Bhi, int tid)
{
    uint32_t stbase = sbase + (uint32_t)s * G2STG_B;
    load_buf(stbase,          Ahi, k0, tid);
    load_buf(stbase + GBUF_B, Bhi, k0, tid);
}

#define HT1(m, n, i0, i1) \
    MMAH_OP(c##m##n##_0, c##m##n##_1, c##m##n##_2, c##m##n##_3, \
            ah##m##_0, ah##m##_1, ah##m##_2, ah##m##_3, bh##n##_##i0, bh##n##_##i1)

#define GEMM2_K16(AOFF0, AOFF1, i0, i1) \
    LDSM_OP(ah0_0, ah0_1, ah0_2, ah0_3, Ah + (AOFF0)); \
    LDSM_OP(ah1_0, ah1_1, ah1_2, ah1_3, Ah + (AOFF1)); \
    HT1(0,0,i0,i1); HT1(0,1,i0,i1); HT1(0,2,i0,i1); HT1(0,3,i0,i1); \
    HT1(1,0,i0,i1); HT1(1,1,i0,i1); HT1(1,2,i0,i1); HT1(1,3,i0,i1)

#define LOAD_B2_KH2(kh2sel) \
    LDSM_OP(bh0_0, bh0_1, bh0_2, bh0_3, Bh + bo0_##kh2sel); \
    LDSM_OP(bh1_0, bh1_1, bh1_2, bh1_3, Bh + bo1_##kh2sel); \
    LDSM_OP(bh2_0, bh2_1, bh2_2, bh2_3, Bh + bo2_##kh2sel); \
    LDSM_OP(bh3_0, bh3_1, bh3_2, bh3_3, Bh + bo3_##kh2sel)

__global__ __launch_bounds__(512, 1)
void out2_kernel(float* __restrict__ out)
{
    extern __shared__ char smem[];
    uint32_t sbase = smem_to_u32(smem);

    const int m0 = (int)blockIdx.x * 128, n0 = (int)blockIdx.y * 128;
    const __half* Ahi = g_Ch_hi + (size_t)m0 * DIM;
    const __half* Bhi = g_Wot_h + (size_t)n0 * DIM;
    float* Cp = out + (size_t)m0 * DIM + n0;
    const int ldc = DIM;

    const int tid  = threadIdx.x;
    const int lane = tid & 31;
    const int wid  = tid >> 5;
    const int wm   = wid >> 2;
    const int wn   = wid & 3;

    DECL_ACC(0,0); DECL_ACC(0,1); DECL_ACC(0,2); DECL_ACC(0,3);
    DECL_ACC(1,0); DECL_ACC(1,1); DECL_ACC(1,2); DECL_ACC(1,3);

    const int NT = DIM / 64;

    g_load_stage2(sbase, 0, 0,  Ahi, Bhi, tid); CP_COMMIT();
    g_load_stage2(sbase, 1, 64, Ahi, Bhi, tid); CP_COMMIT();

    const int ar0 = wm * 32 + ((lane >> 3) & 1) * 8 + (lane & 7);
    const int ar1 = ar0 + 16;
    const int ln16 = lane >> 4;
    const uint32_t ao0_0 = gsw(ar0, 0 + ln16), ao0_1 = gsw(ar0, 2 + ln16);
    const uint32_t ao0_2 = gsw(ar0, 4 + ln16), ao0_3 = gsw(ar0, 6 + ln16);
    const uint32_t ao1_0 = gsw(ar1, 0 + ln16), ao1_1 = gsw(ar1, 2 + ln16);
    const uint32_t ao1_2 = gsw(ar1, 4 + ln16), ao1_3 = gsw(ar1, 6 + ln16);
    const int ln8 = lane >> 3;
    const uint32_t bo0_0 = gsw(wn*32 + 0  + (lane&7), ln8);
    const uint32_t bo1_0 = gsw(wn*32 + 8  + (lane&7), ln8);
    const uint32_t bo2_0 = gsw(wn*32 + 16 + (lane&7), ln8);
    const uint32_t bo3_0 = gsw(wn*32 + 24 + (lane&7), ln8);
    const uint32_t bo0_1 = gsw(wn*32 + 0  + (lane&7), 4 + ln8);
    const uint32_t bo1_1 = gsw(wn*32 + 8  + (lane&7), 4 + ln8);
    const uint32_t bo2_1 = gsw(wn*32 + 16 + (lane&7), 4 + ln8);
    const uint32_t bo3_1 = gsw(wn*32 + 24 + (lane&7), 4 + ln8);

    for (int i = 0; i < NT; i++) {
        CP_WAIT(1);
        __syncthreads();
        int pf = i + 2;
        if (pf < NT)
            g_load_stage2(sbase, pf % 3, pf * 64, Ahi, Bhi, tid);
        CP_COMMIT();

        uint32_t stb = sbase + (uint32_t)(i % 3) * G2STG_B;
        uint32_t Ah = stb, Bh = stb + GBUF_B;

        DECL_F(bh, 0); DECL_F(bh, 1); DECL_F(bh, 2); DECL_F(bh, 3);
        uint32_t ah0_0, ah0_1, ah0_2, ah0_3, ah1_0, ah1_1, ah1_2, ah1_3;

        LOAD_B2_KH2(0);
        GEMM2_K16(ao0_0, ao1_0, 0, 1);
        GEMM2_K16(ao0_1, ao1_1, 2, 3);
        LOAD_B2_KH2(1);
        GEMM2_K16(ao0_2, ao1_2, 0, 1);
        GEMM2_K16(ao0_3, ao1_3, 2, 3);
    }

    STORE_C(0,0); STORE_C(0,1); STORE_C(0,2); STORE_C(0,3);
    STORE_C(1,0); STORE_C(1,1); STORE_C(1,2); STORE_C(1,3);
}

// ===========================================================================
// Fast exp on the FMA pipe
// ===========================================================================
__device__ __forceinline__ float fexp(float x) {
    float y = x * 1.4426950408889634f;
    y = fmaxf(y, -125.0f);
    float fl = floorf(y);
    float t = y - fl;
    float r = 1.5403530e-4f;
    r = fmaf(r, t, 1.3333558e-3f);
    r = fmaf(r, t, 9.6181291e-3f);
    r = fmaf(r, t, 5.5504109e-2f);
    r = fmaf(r, t, 2.4022651e-1f);
    r = fmaf(r, t, 6.9314718e-1f);
    r = fmaf(r, t, 1.0f);
    float s = __int_as_float(((int)fl + 127) << 23);
    return r * s;
}

// ===========================================================================
// RoPE + scale + split: Q/K -> split bf16 (Q scaled); V -> fp16 1-term
// ===========================================================================
__global__ void ropesplit_kernel(const int* __restrict__ pos)
{
    int idx = blockIdx.x * blockDim.x + threadIdx.x;
    const int NQP = SEQ * NH * 64;
    const int NKP = SEQ * NKV * 64;
    const int NVP = SEQ * NKV * 64;
    if (idx >= NQP + NKP + NVP) return;

    if (idx < NQP) {
        int i = idx & 63, h = (idx >> 6) & 31, s = idx >> 11;
        size_t o = (size_t)s * (NH * HDIM) + h * HDIM + i;
        float x1 = g_Q[o], x2 = g_Q[o + 64];
        float p = (float)pos[s];
        float freq = (float)exp2(-(double)i * 0.31143075889569021);
        float sn, cs; sincosf(p * freq, &sn, &cs);
        const float sc = 0.08838834764831845f;
        float y1 = (x1 * cs - x2 * sn) * sc;
        float y2 = (x1 * sn + x2 * cs) * sc;
        __nv_bfloat16 hh, ll;
        split1(y1, hh, ll); g_Qhi[o] = hh;      g_Qlo[o] = ll;
        split1(y2, hh, ll); g_Qhi[o + 64] = hh; g_Qlo[o + 64] = ll;
    } else if (idx < NQP + NKP) {
        int t = idx - NQP;
        int i = t & 63, g = (t >> 6) & 7, s = t >> 9;
        size_t o = (size_t)s * (NKV * HDIM) + g * HDIM + i;
        float x1 = g_K[o], x2 = g_K[o + 64];
        float p = (float)pos[s];
        float freq = (float)exp2(-(double)i * 0.31143075889569021);
        float sn, cs; sincosf(p * freq, &sn, &cs);
        float y1 = x1 * cs - x2 * sn;
        float y2 = x1 * sn + x2 * cs;
        __nv_bfloat16 hh, ll;
        split1(y1, hh, ll); g_Khi[o] = hh;      g_Klo[o] = ll;
        split1(y2, hh, ll); g_Khi[o + 64] = hh; g_Klo[o + 64] = ll;
    } else {
        int t = idx - NQP - NKP;
        int i = t & 63, g = (t >> 6) & 7, s = t >> 9;
        size_t o = (size_t)s * (NKV * HDIM) + g * HDIM + i;
        g_Vh[o]      = __float2half_rn(g_V[o]);
        g_Vh[o + 64] = __float2half_rn(g_V[o + 64]);
    }
}

// ===========================================================================
// HMMA flash attention. S: 3-term split-bf16 (unchanged). PV: 1-term fp16
// (P fp16, V fp16) -> 1/3 the PV MMAs, half the V traffic.
// Stage = Khi + Klo + Vh = 48KB; smem = 64 + 96 + mask = ~161KB.
// ===========================================================================
constexpr int AQ_B     = 32768;
constexpr int AKV_B    = 16384;
constexpr int AST_B    = 3 * AKV_B;            // Khi, Klo, Vh
constexpr int AMSK_OFF = 2 * AQ_B + 2 * AST_B; // 163840
constexpr int ATTN_SMEM = AMSK_OFF + 768;

__device__ __forceinline__ uint32_t asw(int row, int ch) {
    return (uint32_t)(row * 256 + ((ch ^ (row & 7)) << 4));
}
__device__ __forceinline__ uint32_t a_addr(uint32_t base, int m0, int cb, int lane) {
    int row = m0 + ((lane >> 3) & 1) * 8 + (lane & 7);
    return base + asw(row, cb + (lane >> 4));
}
__device__ __forceinline__ uint32_t b_addr(uint32_t base, int n0, int cb, int lane) {
    int row = n0 + (lane & 7);
    return base + asw(row, cb + (lane >> 3));
}
__device__ __forceinline__ uint32_t v_addr(uint32_t base, int t, int nfp, int lane) {
    int g = lane >> 3;
    int row = t * 16 + (g & 1) * 8 + (lane & 7);
    return base + asw(row, nfp * 2 + (g >> 1));
}

__device__ __forceinline__ void load_q_buf(uint32_t dst, const __nv_bfloat16* g,
                                           int q0, int h, int tid) {
#pragma unroll
    for (int j = 0; j < 8; j++) {
        int c = tid * 8 + j;
        int row = c >> 4, ch = c & 15;
        cp16(dst + asw(row, ch),
             g + (size_t)(q0 + row) * (NH * HDIM) + h * HDIM + ch * 8);
    }
}
__device__ __forceinline__ void load_kv_arr(uint32_t dst, const void* gp,
                                            int s0, int gkv, int tid) {
    const __nv_bfloat16* g = (const __nv_bfloat16*)gp;
#pragma unroll
    for (int j = 0; j < 4; j++) {
        int c = tid * 4 + j;
        int row = c >> 4, ch = c & 15;
        cp16(dst + asw(row, ch),
             g + (size_t)(s0 + row) * (NKV * HDIM) + gkv * HDIM + ch * 8);
    }
}

#define DECL_S(n) float s##n##_0, s##n##_1, s##n##_2, s##n##_3
#define ZERO_S(n) s##n##_0 = 0.f; s##n##_1 = 0.f; s##n##_2 = 0.f; s##n##_3 = 0.f
#define DECL_O(n) float o##n##_0 = 0.f, o##n##_1 = 0.f, o##n##_2 = 0.f, o##n##_3 = 0.f

#define SMMA_T(nf, A0,A1,A2,A3, B0,B1) \
    MMA_OP(s##nf##_0, s##nf##_1, s##nf##_2, s##nf##_3, A0,A1,A2,A3, B0,B1)

#define S_NF2(na, nb) do { \
    uint32_t kA0,kA1,kA2,kA3, lA0,lA1,lA2,lA3; \
    uint32_t kB0,kB1,kB2,kB3, lB0,lB1,lB2,lB3; \
    LDSM_OP(kA0,kA1,kA2,kA3, b_addr(KhB, (na)*8, ks2*4, lane)); \
    LDSM_OP(kB0,kB1,kB2,kB3, b_addr(KhB, (nb)*8, ks2*4, lane)); \
    LDSM_OP(lA0,lA1,lA2,lA3, b_addr(KlB, (na)*8, ks2*4, lane)); \
    LDSM_OP(lB0,lB1,lB2,lB3, b_addr(KlB, (nb)*8, ks2*4, lane)); \
    SMMA_T(na, qh0,qh1,qh2,qh3, kA0,kA1); \
    SMMA_T(nb, qh0,qh1,qh2,qh3, kB0,kB1); \
    SMMA_T(na, ql0,ql1,ql2,ql3, kA0,kA1); \
    SMMA_T(nb, ql0,ql1,ql2,ql3, kB0,kB1); \
    SMMA_T(na, qh0,qh1,qh2,qh3, lA0,lA1); \
    SMMA_T(nb, qh0,qh1,qh2,qh3, lB0,lB1); \
    SMMA_T(na, qh4,qh5,qh6,qh7, kA2,kA3); \
    SMMA_T(nb, qh4,qh5,qh6,qh7, kB2,kB3); \
    SMMA_T(na, ql4,ql5,ql6,ql7, kA2,kA3); \
    SMMA_T(nb, ql4,ql5,ql6,ql7, kB2,kB3); \
    SMMA_T(na, qh4,qh5,qh6,qh7, lA2,lA3); \
    SMMA_T(nb, qh4,qh5,qh6,qh7, lB2,lB3); \
} while (0)

#define MASK_NF(nf) do { \
    int lc = (nf) * 8 + ((lane & 3) << 1); \
    float mA = mskp[lc], mB = mskp[lc + 1]; \
    int cg = k0 + lc; \
    s##nf##_0 += (mA > 0.f && (!cz || cg     <= rg0)) ? 0.f : -1e30f; \
    s##nf##_1 += (mB > 0.f && (!cz || cg + 1 <= rg0)) ? 0.f : -1e30f; \
    s##nf##_2 += (mA > 0.f && (!cz || cg     <= rg1)) ? 0.f : -1e30f; \
    s##nf##_3 += (mB > 0.f && (!cz || cg + 1 <= rg1)) ? 0.f : -1e30f; \
} while (0)

#define MAX_NF(nf) \
    mx0 = fmaxf(mx0, fmaxf(s##nf##_0, s##nf##_1)); \
    mx1 = fmaxf(mx1, fmaxf(s##nf##_2, s##nf##_3))

#define EXP_NF(nf) \
    s##nf##_0 = fexp(s##nf##_0 - mn0); sum0 += s##nf##_0; \
    s##nf##_1 = fexp(s##nf##_1 - mn0); sum0 += s##nf##_1; \
    s##nf##_2 = fexp(s##nf##_2 - mn1); sum1 += s##nf##_2; \
    s##nf##_3 = fexp(s##nf##_3 - mn1); sum1 += s##nf##_3

#define SCALE_O(n) \
    o##n##_0 *= al0; o##n##_1 *= al0; o##n##_2 *= al1; o##n##_3 *= al1

#define OMMAH_T(on, A0,A1,A2,A3, B0,B1) \
    MMAH_OP(o##on##_0, o##on##_1, o##on##_2, o##on##_3, A0,A1,A2,A3, B0,B1)

// 1-term fp16 PV: one LDSMT + two MMAs per nfp
#define PV_NFP(tt, nfp, oA, oB) do { \
    uint32_t vh0,vh1,vh2,vh3; \
    LDSMT_OP(vh0,vh1,vh2,vh3, v_addr(VhB, tt, nfp, lane)); \
    OMMAH_T(oA, pa0,pa1,pa2,pa3, vh0,vh1); \
    OMMAH_T(oB, pa0,pa1,pa2,pa3, vh2,vh3); \
} while (0)

#define PVT(e, f, tt) do { \
    uint32_t pa0,pa1,pa2,pa3; \
    pa0 = f2h2(s##e##_0, s##e##_1); \
    pa1 = f2h2(s##e##_2, s##e##_3); \
    pa2 = f2h2(s##f##_0, s##f##_1); \
    pa3 = f2h2(s##f##_2, s##f##_3); \
    PV_NFP(tt, 0, 0, 1);  PV_NFP(tt, 1, 2, 3); \
    PV_NFP(tt, 2, 4, 5);  PV_NFP(tt, 3, 6, 7); \
    PV_NFP(tt, 4, 8, 9);  PV_NFP(tt, 5, 10, 11); \
    PV_NFP(tt, 6, 12, 13); PV_NFP(tt, 7, 14, 15); \
} while (0)

#define EPI_O(n) do { \
    __half2 hv = __floats2half2_rn(o##n##_0 * il0, o##n##_1 * il0); \
    *(__half2*)(g_Ch_hi + ro0 + (n) * 8) = hv; \
    hv = __floats2half2_rn(o##n##_2 * il1, o##n##_3 * il1); \
    *(__half2*)(g_Ch_hi + ro1 + (n) * 8) = hv; \
} while (0)

__global__ __launch_bounds__(256, 1)
void attn_mma_kernel(const float* __restrict__ amask)
{
    extern __shared__ char smem[];
    uint32_t sbase = smem_to_u32(smem);
    float* msk = (float*)(smem + AMSK_OFF);   // 2 slots x 64

    const int h    = blockIdx.x;
    const int qt   = (int)gridDim.y - 1 - (int)blockIdx.y;
    const int gkv  = h >> 2;
    const int tid  = threadIdx.x;
    const int lane = tid & 31;
    const int wid  = tid >> 5;
    const int q0   = qt * 128;

    const uint32_t QhB = sbase, QlB = sbase + AQ_B;

    load_q_buf(QhB, g_Qhi, q0, h, tid);
    load_q_buf(QlB, g_Qlo, q0, h, tid);
    {
        uint32_t st = sbase + 2 * AQ_B;
        load_kv_arr(st,             g_Khi, 0, gkv, tid);
        load_kv_arr(st + AKV_B,     g_Klo, 0, gkv, tid);
        load_kv_arr(st + 2 * AKV_B, g_Vh,  0, gkv, tid);
    }
    CP_COMMIT();

    DECL_O(0);  DECL_O(1);  DECL_O(2);  DECL_O(3);
    DECL_O(4);  DECL_O(5);  DECL_O(6);  DECL_O(7);
    DECL_O(8);  DECL_O(9);  DECL_O(10); DECL_O(11);
    DECL_O(12); DECL_O(13); DECL_O(14); DECL_O(15);
    float m0 = -1e30f, m1 = -1e30f, l0 = 0.f, l1 = 0.f;

    const int rg0 = q0 + wid * 16 + (lane >> 2);
    const int rg1 = rg0 + 8;
    const int ktmax = 2 * qt + 1;

    for (int kt = 0; kt <= ktmax; kt++) {
        const int k0 = kt * 64;
        const uint32_t stg = sbase + 2 * AQ_B + (uint32_t)(kt & 1) * AST_B;
        float* mskp = msk + (kt & 1) * 64;

        if (tid < 64) mskp[tid] = amask[k0 + tid];
        CP_WAIT(0);               // stage kt (and Q on kt==0) resident
        __syncthreads();          // visibility + all reads of stage kt-1 done

        if (kt < ktmax) {
            uint32_t nst = sbase + 2 * AQ_B + (uint32_t)((kt + 1) & 1) * AST_B;
            int ns = (kt + 1) * 64;
            load_kv_arr(nst,             g_Khi, ns, gkv, tid);
            load_kv_arr(nst + AKV_B,     g_Klo, ns, gkv, tid);
            load_kv_arr(nst + 2 * AKV_B, g_Vh,  ns, gkv, tid);
            CP_COMMIT();
        }

        const uint32_t KhB = stg, KlB = stg + AKV_B;
        const uint32_t VhB = stg + 2 * AKV_B;
        const bool cz = (kt >= 2 * qt);

        DECL_S(0); DECL_S(1); DECL_S(2); DECL_S(3);
        DECL_S(4); DECL_S(5); DECL_S(6); DECL_S(7);
        ZERO_S(0); ZERO_S(1); ZERO_S(2); ZERO_S(3);
        ZERO_S(4); ZERO_S(5); ZERO_S(6); ZERO_S(7);

#pragma unroll
        for (int ks2 = 0; ks2 < 4; ks2++) {
            uint32_t qh0, qh1, qh2, qh3, qh4, qh5, qh6, qh7;
            uint32_t ql0, ql1, ql2, ql3, ql4, ql5, ql6, ql7;
            LDSM_OP(qh0, qh1, qh2, qh3, a_addr(QhB, wid * 16, ks2 * 4, lane));
            LDSM_OP(qh4, qh5, qh6, qh7, a_addr(QhB, wid * 16, ks2 * 4 + 2, lane));
            LDSM_OP(ql0, ql1, ql2, ql3, a_addr(QlB, wid * 16, ks2 * 4, lane));
            LDSM_OP(ql4, ql5, ql6, ql7, a_addr(QlB, wid * 16, ks2 * 4 + 2, lane));
            S_NF2(0, 1); S_NF2(2, 3); S_NF2(4, 5); S_NF2(6, 7);
        }

        MASK_NF(0); MASK_NF(1); MASK_NF(2); MASK_NF(3);
        MASK_NF(4); MASK_NF(5); MASK_NF(6); MASK_NF(7);

        float mx0 = -1e30f, mx1 = -1e30f;
        MAX_NF(0); MAX_NF(1); MAX_NF(2); MAX_NF(3);
        MAX_NF(4); MAX_NF(5); MAX_NF(6); MAX_NF(7);
        mx0 = fmaxf(mx0, __shfl_xor_sync(0xffffffffu, mx0, 1, 4));
        mx0 = fmaxf(mx0, __shfl_xor_sync(0xffffffffu, mx0, 2, 4));
        mx1 = fmaxf(mx1, __shfl_xor_sync(0xffffffffu, mx1, 1, 4));
        mx1 = fmaxf(mx1, __shfl_xor_sync(0xffffffffu, mx1, 2, 4));

        float mn0 = fmaxf(m0, mx0), mn1 = fmaxf(m1, mx1);
        float al0 = fexp(m0 - mn0), al1 = fexp(m1 - mn1);
        m0 = mn0; m1 = mn1;

        float sum0 = 0.f, sum1 = 0.f;
        EXP_NF(0); EXP_NF(1); EXP_NF(2); EXP_NF(3);
        EXP_NF(4); EXP_NF(5); EXP_NF(6); EXP_NF(7);
        sum0 += __shfl_xor_sync(0xffffffffu, sum0, 1, 4);
        sum0 += __shfl_xor_sync(0xffffffffu, sum0, 2, 4);
        sum1 += __shfl_xor_sync(0xffffffffu, sum1, 1, 4);
        sum1 += __shfl_xor_sync(0xffffffffu, sum1, 2, 4);
        l0 = l0 * al0 + sum0;
        l1 = l1 * al1 + sum1;

        SCALE_O(0);  SCALE_O(1);  SCALE_O(2);  SCALE_O(3);
        SCALE_O(4);  SCALE_O(5);  SCALE_O(6);  SCALE_O(7);
        SCALE_O(8);  SCALE_O(9);  SCALE_O(10); SCALE_O(11);
        SCALE_O(12); SCALE_O(13); SCALE_O(14); SCALE_O(15);

        PVT(0, 1, 0); PVT(2, 3, 1); PVT(4, 5, 2); PVT(6, 7, 3);
    }

    const float il0 = 1.0f / l0, il1 = 1.0f / l1;
    const size_t ro0 = (size_t)rg0 * DIM + h * HDIM + ((lane & 3) << 1);
    const size_t ro1 = ro0 + (size_t)8 * DIM;
    EPI_O(0);  EPI_O(1);  EPI_O(2);  EPI_O(3);
    EPI_O(4);  EPI_O(5);  EPI_O(6);  EPI_O(7);
    EPI_O(8);  EPI_O(9);  EPI_O(10); EPI_O(11);
    EPI_O(12); EPI_O(13); EPI_O(14); EPI_O(15);
}

// ===========================================================================
extern "C" void kernel_launch(void* const* d_in, const int* in_sizes, int n_in,
                              void* d_out, int out_size)
{
    const float* X   = (const float*)d_in[0];
    const float* am  = (const float*)d_in[1];
    const int*   pos = (const int*)  d_in[2];
    const float* wq  = (const float*)d_in[3];
    const float* wk  = (const float*)d_in[4];
    const float* wv  = (const float*)d_in[5];
    const float* wo  = (const float*)d_in[6];
    float* out = (float*)d_out;

    (void)in_sizes; (void)n_in; (void)out_size;

    // 1. Split conversions
    xsplit_kernel<<<(SEQ * DIM / 4 + 255) / 256, 256>>>(X, SEQ * DIM / 4);
    wsplit_t_kernel<<<dim3(4096 / 32, 4096 / 32), 256>>>(wq, 4096, 0);
    wsplit_t_kernel<<<dim3(1024 / 32, 4096 / 32), 256>>>(wk, 1024, 4096);
    wsplit_t_kernel<<<dim3(1024 / 32, 4096 / 32), 256>>>(wv, 1024, 5120);
    wsplit_wo_kernel<<<dim3(4096 / 32, 4096 / 32), 256>>>(wo);

    // 2. QKV projection (HMMA split-bf16 3-term, CTA 128x256)
    cudaFuncSetAttribute((const void*)qkv3_kernel,
                         cudaFuncAttributeMaxDynamicSharedMemorySize, QKV_SMEM);
    qkv3_kernel<<<dim3(16, 24), 512, QKV_SMEM>>>();

    // 3. RoPE + scale + split of Q/K (bf16) and V (fp16)
    int tot = SEQ * NH * 64 + 2 * SEQ * NKV * 64;
    ropesplit_kernel<<<(tot + 255) / 256, 256>>>(pos);

    // 4. HMMA flash attention (3-term S, 1-term fp16 PV)
    cudaFuncSetAttribute((const void*)attn_mma_kernel,
                         cudaFuncAttributeMaxDynamicSharedMemorySize, ATTN_SMEM);
    attn_mma_kernel<<<dim3(NH, SEQ / 128), 256, ATTN_SMEM>>>(am);

    // 5. Output projection (pure fp16 1-term HMMA)
    cudaFuncSetAttribute((const void*)out2_kernel,
                         cudaFuncAttributeMaxDynamicSharedMemorySize, GEMM2_SMEM);
    out2_kernel<<<dim3(16, 32), 512, GEMM2_SMEM>>>(out);
}